// round 12
// baseline (speedup 1.0000x reference)
#include <cuda_runtime.h>
#include <cuda_bf16.h>
#include <math.h>
#include <cstdint>

#define NN      16384
#define EE      262144
#define HID     128
#define NGAUSS  50
#define NINTER  6
#define NTAB    4096
#define NBLK    128
#define DMAX    8.6610f
#define DELTA   (DMAX / (float)(NTAB - 1))
#define GSPACE  (10.0f / 49.0f)
#define GCOEFF  (-0.5f / (GSPACE * GSPACE))
#define LOG2F_C 0.69314718055994530942f
#define PI_O10  0.31415926535897932f

// ---------------- device scratch ----------------
__device__ float g_d[EE];
__device__ int   g_perm[EE];               // packed (t0 << 16) | src
__device__ float g_pw[EE];                 // lerp weight
__device__ int   g_start[NN + 1];
__device__ int   g_cnt[NN];
__device__ float g_h[NN * HID];            // fp32 residual stream
__device__ __nv_bfloat16 g_xb[NN * HID];
__device__ __nv_bfloat16 g_Hb[NINTER * NTAB * HID];
__device__ __nv_bfloat16 g_Tb[NINTER * NTAB * HID];
__device__ float g_sum;
__device__ volatile unsigned g_bar_gen;
__device__ unsigned g_bar_count;

__device__ __forceinline__ float sspf(float x) {
    float sp = (x > 15.0f) ? x : log1pf(expf(x));
    return sp - LOG2F_C;
}

// ---------------- prep kernels ----------------
__global__ void zero_kernel() {
    int i = blockIdx.x * blockDim.x + threadIdx.x;
    if (i < NN) g_cnt[i] = 0;
    if (i == 0) g_sum = 0.0f;
}

__global__ void prep_kernel(const float* __restrict__ pos, const int* __restrict__ ei) {
    int e = blockIdx.x * blockDim.x + threadIdx.x;
    if (e >= EE) return;
    int s = ei[e];
    int t = ei[EE + e];
    float dx = pos[3 * s + 0] - pos[3 * t + 0];
    float dy = pos[3 * s + 1] - pos[3 * t + 1];
    float dz = pos[3 * s + 2] - pos[3 * t + 2];
    g_d[e] = sqrtf(dx * dx + dy * dy + dz * dz);
    atomicAdd(&g_cnt[t], 1);
}

__global__ void scan_kernel() {
    __shared__ int part[1024];
    int tid = threadIdx.x;
    int base = tid * 16;
    int loc[16];
    int s = 0;
#pragma unroll
    for (int i = 0; i < 16; i++) { loc[i] = g_cnt[base + i]; s += loc[i]; }
    part[tid] = s;
    __syncthreads();
    for (int off = 1; off < 1024; off <<= 1) {
        int v = part[tid];
        int add = (tid >= off) ? part[tid - off] : 0;
        __syncthreads();
        part[tid] = v + add;
        __syncthreads();
    }
    int excl = (tid == 0) ? 0 : part[tid - 1];
#pragma unroll
    for (int i = 0; i < 16; i++) {
        g_start[base + i] = excl;
        g_cnt[base + i] = excl;
        excl += loc[i];
    }
    if (tid == 1023) g_start[NN] = excl;
}

__global__ void scatter_kernel(const int* __restrict__ ei) {
    int e = blockIdx.x * blockDim.x + threadIdx.x;
    if (e >= EE) return;
    int t = ei[EE + e];
    int s = ei[e];
    float f = g_d[e] * (1.0f / DELTA);
    int t0 = (int)f;
    t0 = min(t0, NTAB - 2);
    float w = f - (float)t0;
    int p = atomicAdd(&g_cnt[t], 1);
    g_perm[p] = (t0 << 16) | s;
    g_pw[p] = w;
}

__global__ void tableH_kernel(const float* __restrict__ Wf1, const float* __restrict__ bf1) {
    int inter = blockIdx.y;
    int tbase = blockIdx.x * 8;
    __shared__ float W1s[NGAUSS * HID];
    __shared__ float eas[8][NGAUSS];
    const float* W1 = Wf1 + inter * NGAUSS * HID;
    for (int i = threadIdx.x; i < NGAUSS * HID; i += 128) W1s[i] = W1[i];
    for (int i = threadIdx.x; i < 8 * NGAUSS; i += 128) {
        int r = i / NGAUSS, k = i % NGAUSS;
        float dt = (tbase + r) * DELTA;
        float u = dt - k * GSPACE;
        eas[r][k] = expf(GCOEFF * u * u);
    }
    __syncthreads();
    float b = bf1[inter * HID + threadIdx.x];
#pragma unroll
    for (int r = 0; r < 8; r++) {
        float s = b;
#pragma unroll
        for (int k = 0; k < NGAUSS; k++) s += eas[r][k] * W1s[k * HID + threadIdx.x];
        g_Hb[(size_t)(inter * NTAB + tbase + r) * HID + threadIdx.x] = __float2bfloat16(sspf(s));
    }
}

// ---------------- MMA helpers ----------------
#define MMA16816(d, a, b0, b1) \
    asm volatile("mma.sync.aligned.m16n8k16.row.col.f32.bf16.bf16.f32 " \
        "{%0,%1,%2,%3}, {%4,%5,%6,%7}, {%8,%9}, {%0,%1,%2,%3};" \
        : "+f"((d)[0]), "+f"((d)[1]), "+f"((d)[2]), "+f"((d)[3]) \
        : "r"((a)[0]), "r"((a)[1]), "r"((a)[2]), "r"((a)[3]), "r"(b0), "r"(b1))

// ---------------- standalone GEMM (filter tables) ----------------
__global__ __launch_bounds__(256) void gemm_filt(
    const __nv_bfloat16* __restrict__ A, const float* __restrict__ W,
    const float* __restrict__ bias, __nv_bfloat16* __restrict__ outB,
    size_t aStride, size_t wStride, size_t bStride, size_t oStride)
{
    __shared__ __nv_bfloat16 sBhi[128][72];
    __shared__ __nv_bfloat16 sBlo[128][72];

    A += (size_t)blockIdx.y * aStride;
    W += (size_t)blockIdx.y * wStride;
    bias += (size_t)blockIdx.y * bStride;
    outB += (size_t)blockIdx.y * oStride;

    const int tid = threadIdx.x;
    const int w = tid >> 5, lane = tid & 31;
    const int wm = w >> 1, wn = w & 1;
    const int g = lane >> 2, tg = lane & 3;
    const int row0 = blockIdx.x * 128;

    float acc[2][8][4] = {};
    const __nv_bfloat16* aBase = A + (size_t)(row0 + wm * 32 + g) * 128;

    for (int kh = 0; kh < 2; kh++) {
        __syncthreads();
        for (int idx = tid; idx < 64 * 128; idx += 256) {
            int kp = idx >> 7, n = idx & 127;
            float v = W[(size_t)(kh * 64 + kp) * 128 + n];
            __nv_bfloat16 h = __float2bfloat16(v);
            sBhi[n][kp] = h;
            sBlo[n][kp] = __float2bfloat16(v - __bfloat162float(h));
        }
        __syncthreads();
#pragma unroll
        for (int ks = 0; ks < 4; ks++) {
            int kc = kh * 64 + ks * 16 + tg * 2;
            uint32_t af[2][4];
#pragma unroll
            for (int mt = 0; mt < 2; mt++) {
                const __nv_bfloat16* rp = aBase + (size_t)mt * 16 * 128;
                af[mt][0] = *(const uint32_t*)(rp + kc);
                af[mt][1] = *(const uint32_t*)(rp + 8 * 128 + kc);
                af[mt][2] = *(const uint32_t*)(rp + kc + 8);
                af[mt][3] = *(const uint32_t*)(rp + 8 * 128 + kc + 8);
            }
            int c = ks * 16 + tg * 2;
#pragma unroll
            for (int nt = 0; nt < 8; nt++) {
                int n = wn * 64 + nt * 8 + g;
                uint32_t bh0 = *(const uint32_t*)&sBhi[n][c];
                uint32_t bh1 = *(const uint32_t*)&sBhi[n][c + 8];
                uint32_t bl0 = *(const uint32_t*)&sBlo[n][c];
                uint32_t bl1 = *(const uint32_t*)&sBlo[n][c + 8];
#pragma unroll
                for (int mt = 0; mt < 2; mt++) {
                    MMA16816(acc[mt][nt], af[mt], bh0, bh1);
                    MMA16816(acc[mt][nt], af[mt], bl0, bl1);
                }
            }
        }
    }

#pragma unroll
    for (int mt = 0; mt < 2; mt++) {
        int r0 = row0 + wm * 32 + mt * 16 + g;
        int r1 = r0 + 8;
        float s0 = 0.5f * (cosf((float)r0 * DELTA * PI_O10) + 1.0f);
        float s1 = 0.5f * (cosf((float)r1 * DELTA * PI_O10) + 1.0f);
#pragma unroll
        for (int nt = 0; nt < 8; nt++) {
            int cc = wn * 64 + nt * 8 + tg * 2;
            float2 bv = *(const float2*)(bias + cc);
            float vx0 = (acc[mt][nt][0] + bv.x) * s0;
            float vy0 = (acc[mt][nt][1] + bv.y) * s0;
            float vx1 = (acc[mt][nt][2] + bv.x) * s1;
            float vy1 = (acc[mt][nt][3] + bv.y) * s1;
            *(__nv_bfloat162*)(outB + (size_t)r0 * 128 + cc) = __floats2bfloat162_rn(vx0, vy0);
            *(__nv_bfloat162*)(outB + (size_t)r1 * 128 + cc) = __floats2bfloat162_rn(vx1, vy1);
        }
    }
}

// ---------------- pipelined weight staging helpers ----------------
template <int NC>
__device__ __forceinline__ void ldg_chunk(const float* __restrict__ W, int kh,
                                          float* wreg, int tid) {
#pragma unroll
    for (int i = 0; i < 64 * NC / 256; i++) {
        int flat = tid + i * 256;
        int kp = flat / NC, n = flat % NC;
        wreg[i] = W[(size_t)(kh * 64 + kp) * NC + n];
    }
}
template <int NC>
__device__ __forceinline__ void sts_chunk(const float* wreg,
                                          __nv_bfloat16* hi, __nv_bfloat16* lo, int tid) {
#pragma unroll
    for (int i = 0; i < 64 * NC / 256; i++) {
        int flat = tid + i * 256;
        int kp = flat / NC, n = flat % NC;
        float v = wreg[i];
        __nv_bfloat16 h = __float2bfloat16(v);
        hi[n * 72 + kp] = h;
        lo[n * 72 + kp] = __float2bfloat16(v - __bfloat162float(h));
    }
}

template <int NT>
__device__ __forceinline__ void mma_half(
    const __nv_bfloat16* __restrict__ A, int lda, int kh,
    const __nv_bfloat16* hi, const __nv_bfloat16* lo,
    int wm, int wn, int g, int tg, float acc[2][NT][4])
{
    const __nv_bfloat16* rp0 = A + (wm * 32 + g) * lda;
    const int colbase = wn * (NT * 8);
#pragma unroll
    for (int ks = 0; ks < 4; ks++) {
        int kc = kh * 64 + ks * 16 + tg * 2;
        uint32_t af[2][4];
#pragma unroll
        for (int mt = 0; mt < 2; mt++) {
            const __nv_bfloat16* rp = rp0 + mt * 16 * lda;
            af[mt][0] = *(const uint32_t*)(rp + kc);
            af[mt][1] = *(const uint32_t*)(rp + 8 * lda + kc);
            af[mt][2] = *(const uint32_t*)(rp + kc + 8);
            af[mt][3] = *(const uint32_t*)(rp + 8 * lda + kc + 8);
        }
        int c = ks * 16 + tg * 2;
#pragma unroll
        for (int nt = 0; nt < NT; nt++) {
            int n = colbase + nt * 8 + g;
            uint32_t bh0 = *(const uint32_t*)(hi + n * 72 + c);
            uint32_t bh1 = *(const uint32_t*)(hi + n * 72 + c + 8);
            uint32_t bl0 = *(const uint32_t*)(lo + n * 72 + c);
            uint32_t bl1 = *(const uint32_t*)(lo + n * 72 + c + 8);
#pragma unroll
            for (int mt = 0; mt < 2; mt++) {
                MMA16816(acc[mt][nt], af[mt], bh0, bh1);
                MMA16816(acc[mt][nt], af[mt], bl0, bl1);
            }
        }
    }
}

// ---------------- edge gather term ----------------
__device__ __forceinline__ void edge_acc(const __nv_bfloat16* xb, const __nv_bfloat16* Tb,
                                         int pk, float wt, int lane, float4& acc) {
    int s = pk & 0xFFFF;
    int t0 = pk >> 16;
    uint2 xv = ((const uint2*)(xb + (size_t)s * 128))[lane];
    uint2 a0 = ((const uint2*)(Tb + (size_t)t0 * 128))[lane];
    uint2 a1 = ((const uint2*)(Tb + (size_t)(t0 + 1) * 128))[lane];
    float2 x0 = __bfloat1622float2(*(__nv_bfloat162*)&xv.x);
    float2 x1 = __bfloat1622float2(*(__nv_bfloat162*)&xv.y);
    float2 p0 = __bfloat1622float2(*(__nv_bfloat162*)&a0.x);
    float2 p1 = __bfloat1622float2(*(__nv_bfloat162*)&a0.y);
    float2 q0 = __bfloat1622float2(*(__nv_bfloat162*)&a1.x);
    float2 q1 = __bfloat1622float2(*(__nv_bfloat162*)&a1.y);
    float w0 = 1.0f - wt;
    acc.x += x0.x * (w0 * p0.x + wt * q0.x);
    acc.y += x0.y * (w0 * p0.y + wt * q0.y);
    acc.z += x1.x * (w0 * p1.x + wt * q1.x);
    acc.w += x1.y * (w0 * p1.y + wt * q1.y);
}

// ---------------- grid-wide sense-reversal barrier ----------------
__device__ __forceinline__ void grid_sync() {
    __syncthreads();
    if (threadIdx.x == 0) {
        __threadfence();                       // release: publish xb stores
        unsigned gen = g_bar_gen;
        unsigned t = atomicAdd(&g_bar_count, 1u);
        if (t == NBLK - 1) {
            g_bar_count = 0;
            __threadfence();
            g_bar_gen = gen + 1;
        } else {
            while (g_bar_gen == gen) {}
        }
        __threadfence();                       // acquire: invalidate L1
    }
    __syncthreads();
}

// ---------------- persistent mega-kernel: emb + x0 + 6x(agg + update) + readout ----------------
__global__ __launch_bounds__(256) void mega_kernel(
    const int* __restrict__ z, const float* __restrict__ emb,
    const float* __restrict__ Wl1, const float* __restrict__ Wl2,
    const float* __restrict__ bl2, const float* __restrict__ Wl,
    const float* __restrict__ bl,  const float* __restrict__ Wo1,
    const float* __restrict__ bo1, const float* __restrict__ Wo2)
{
    extern __shared__ __align__(16) char smem_raw[];
    __nv_bfloat16* sWhi0 = (__nv_bfloat16*)smem_raw;     // 128*72
    __nv_bfloat16* sWlo0 = sWhi0 + 128 * 72;
    __nv_bfloat16* sWhi1 = sWlo0 + 128 * 72;
    __nv_bfloat16* sWlo1 = sWhi1 + 128 * 72;
    __nv_bfloat16* sT    = sWlo1 + 128 * 72;             // 128*136
    __nv_bfloat16* sHn   = sT + 128 * 136;               // 128*136

    const int tid = threadIdx.x;
    const int w = tid >> 5, lane = tid & 31;
    const int wm = w >> 1, wn = w & 1;
    const int g = lane >> 2, tg = lane & 3;
    const int row0 = blockIdx.x * 128;

    float wreg[32];

    // ---- emb: h (fp32 global) + hb (smem bf16) for own tile ----
    for (int idx = tid; idx < 128 * 128; idx += 256) {
        int r = idx >> 7, c = idx & 127;
        float v = emb[z[row0 + r] * HID + c];
        g_h[(size_t)(row0 + r) * HID + c] = v;
        sHn[r * 136 + c] = __float2bfloat16(v);
    }
    __syncthreads();

    // ---- x0 = hb @ Wl1[0] -> g_xb ----
    {
        ldg_chunk<128>(Wl1, 0, wreg, tid);
        sts_chunk<128>(wreg, sWhi0, sWlo0, tid);
        __syncthreads();
        float accx[2][8][4] = {};
        ldg_chunk<128>(Wl1, 1, wreg, tid);
        mma_half<8>(sHn, 136, 0, sWhi0, sWlo0, wm, wn, g, tg, accx);
        sts_chunk<128>(wreg, sWhi1, sWlo1, tid);
        __syncthreads();
        mma_half<8>(sHn, 136, 1, sWhi1, sWlo1, wm, wn, g, tg, accx);
#pragma unroll
        for (int mt = 0; mt < 2; mt++) {
            int r0 = row0 + wm * 32 + mt * 16 + g;
            int r1 = r0 + 8;
#pragma unroll
            for (int nt = 0; nt < 8; nt++) {
                int cc = wn * 64 + nt * 8 + tg * 2;
                *(__nv_bfloat162*)(g_xb + (size_t)r0 * 128 + cc) =
                    __floats2bfloat162_rn(accx[mt][nt][0], accx[mt][nt][1]);
                *(__nv_bfloat162*)(g_xb + (size_t)r1 * 128 + cc) =
                    __floats2bfloat162_rn(accx[mt][nt][2], accx[mt][nt][3]);
            }
        }
    }
    grid_sync();

    for (int i = 0; i < NINTER; i++) {
        const float* Wl2i = Wl2 + (size_t)i * HID * HID;
        const float* Wli  = Wl  + (size_t)i * HID * HID;
        const float* bl2i = bl2 + (size_t)i * HID;
        const float* bli  = bl  + (size_t)i * HID;
        const __nv_bfloat16* Tbi = g_Tb + (size_t)i * NTAB * HID;
        const bool last = (i == NINTER - 1);
        const float* W3 = last ? Wo1 : (Wl1 + (size_t)(i + 1) * HID * HID);

        // ---- agg for own 128 nodes -> sHn ----
        {
            for (int nn = 0; nn < 16; nn++) {
                int nl = w * 16 + nn;
                int node = row0 + nl;
                int b = g_start[node];
                int e = g_start[node + 1];
                float4 acc = make_float4(0.f, 0.f, 0.f, 0.f);
                int j = b;
                for (; j + 4 <= e; j += 4) {
                    int pk0 = g_perm[j],     pk1 = g_perm[j + 1];
                    int pk2 = g_perm[j + 2], pk3 = g_perm[j + 3];
                    float w0 = g_pw[j],     w1 = g_pw[j + 1];
                    float w2 = g_pw[j + 2], w3 = g_pw[j + 3];
                    edge_acc(g_xb, Tbi, pk0, w0, lane, acc);
                    edge_acc(g_xb, Tbi, pk1, w1, lane, acc);
                    edge_acc(g_xb, Tbi, pk2, w2, lane, acc);
                    edge_acc(g_xb, Tbi, pk3, w3, lane, acc);
                }
                for (; j < e; j++) edge_acc(g_xb, Tbi, g_perm[j], g_pw[j], lane, acc);
                __nv_bfloat162 o0 = __floats2bfloat162_rn(acc.x, acc.y);
                __nv_bfloat162 o1 = __floats2bfloat162_rn(acc.z, acc.w);
                uint2 ov;
                ov.x = *(uint32_t*)&o0;
                ov.y = *(uint32_t*)&o1;
                *(uint2*)(sHn + nl * 136 + lane * 4) = ov;
            }
        }
        // (sync inside stage-1 staging orders sHn writes before reads)

        // ---- stage 1: t = ssp(sHn @ Wl2 + bl2) -> sT ----
        ldg_chunk<128>(Wl2i, 0, wreg, tid);
        sts_chunk<128>(wreg, sWhi0, sWlo0, tid);
        __syncthreads();
        {
            float acc1[2][8][4] = {};
            ldg_chunk<128>(Wl2i, 1, wreg, tid);
            mma_half<8>(sHn, 136, 0, sWhi0, sWlo0, wm, wn, g, tg, acc1);
            sts_chunk<128>(wreg, sWhi1, sWlo1, tid);
            __syncthreads();

            ldg_chunk<128>(Wli, 0, wreg, tid);
            mma_half<8>(sHn, 136, 1, sWhi1, sWlo1, wm, wn, g, tg, acc1);
            sts_chunk<128>(wreg, sWhi0, sWlo0, tid);
#pragma unroll
            for (int mt = 0; mt < 2; mt++) {
                int r0 = wm * 32 + mt * 16 + g;
                int r1 = r0 + 8;
#pragma unroll
                for (int nt = 0; nt < 8; nt++) {
                    int cc = wn * 64 + nt * 8 + tg * 2;
                    float2 bv = *(const float2*)(bl2i + cc);
                    float vx0 = sspf(acc1[mt][nt][0] + bv.x);
                    float vy0 = sspf(acc1[mt][nt][1] + bv.y);
                    float vx1 = sspf(acc1[mt][nt][2] + bv.x);
                    float vy1 = sspf(acc1[mt][nt][3] + bv.y);
                    *(__nv_bfloat162*)(sT + r0 * 136 + cc) = __floats2bfloat162_rn(vx0, vy0);
                    *(__nv_bfloat162*)(sT + r1 * 136 + cc) = __floats2bfloat162_rn(vx1, vy1);
                }
            }
        }
        __syncthreads();

        // ---- stage 2: hn = t @ Wl + bl + h -> h (fp32) + sHn (bf16) ----
        {
            float acc2[2][8][4] = {};
            ldg_chunk<128>(Wli, 1, wreg, tid);
            mma_half<8>(sT, 136, 0, sWhi0, sWlo0, wm, wn, g, tg, acc2);
            sts_chunk<128>(wreg, sWhi1, sWlo1, tid);
            __syncthreads();

            if (!last) ldg_chunk<128>(W3, 0, wreg, tid);
            else       ldg_chunk<64>(W3, 0, wreg, tid);
            mma_half<8>(sT, 136, 1, sWhi1, sWlo1, wm, wn, g, tg, acc2);
            if (!last) sts_chunk<128>(wreg, sWhi0, sWlo0, tid);
            else       sts_chunk<64>(wreg, sWhi0, sWlo0, tid);
#pragma unroll
            for (int mt = 0; mt < 2; mt++) {
                int r0 = wm * 32 + mt * 16 + g;
                int r1 = r0 + 8;
                float* h0p = g_h + (size_t)(row0 + r0) * 128;
                float* h1p = g_h + (size_t)(row0 + r1) * 128;
#pragma unroll
                for (int nt = 0; nt < 8; nt++) {
                    int cc = wn * 64 + nt * 8 + tg * 2;
                    float2 bv = *(const float2*)(bli + cc);
                    float2 e0 = *(const float2*)(h0p + cc);
                    float2 e1 = *(const float2*)(h1p + cc);
                    float vx0 = acc2[mt][nt][0] + bv.x + e0.x;
                    float vy0 = acc2[mt][nt][1] + bv.y + e0.y;
                    float vx1 = acc2[mt][nt][2] + bv.x + e1.x;
                    float vy1 = acc2[mt][nt][3] + bv.y + e1.y;
                    *(float2*)(h0p + cc) = make_float2(vx0, vy0);
                    *(float2*)(h1p + cc) = make_float2(vx1, vy1);
                    *(__nv_bfloat162*)(sHn + r0 * 136 + cc) = __floats2bfloat162_rn(vx0, vy0);
                    *(__nv_bfloat162*)(sHn + r1 * 136 + cc) = __floats2bfloat162_rn(vx1, vy1);
                }
            }
        }
        __syncthreads();

        // ---- stage 3: next x -> g_xb, or readout ----
        if (!last) {
            float acc3[2][8][4] = {};
            ldg_chunk<128>(W3, 1, wreg, tid);
            mma_half<8>(sHn, 136, 0, sWhi0, sWlo0, wm, wn, g, tg, acc3);
            sts_chunk<128>(wreg, sWhi1, sWlo1, tid);
            __syncthreads();
            mma_half<8>(sHn, 136, 1, sWhi1, sWlo1, wm, wn, g, tg, acc3);
#pragma unroll
            for (int mt = 0; mt < 2; mt++) {
                int r0 = row0 + wm * 32 + mt * 16 + g;
                int r1 = r0 + 8;
#pragma unroll
                for (int nt = 0; nt < 8; nt++) {
                    int cc = wn * 64 + nt * 8 + tg * 2;
                    *(__nv_bfloat162*)(g_xb + (size_t)r0 * 128 + cc) =
                        __floats2bfloat162_rn(acc3[mt][nt][0], acc3[mt][nt][1]);
                    *(__nv_bfloat162*)(g_xb + (size_t)r1 * 128 + cc) =
                        __floats2bfloat162_rn(acc3[mt][nt][2], acc3[mt][nt][3]);
                }
            }
            grid_sync();   // publish xb, invalidate L1, all blocks aligned
        } else {
            float acc3[2][4][4] = {};
            ldg_chunk<64>(W3, 1, wreg, tid);
            mma_half<4>(sHn, 136, 0, sWhi0, sWlo0, wm, wn, g, tg, acc3);
            sts_chunk<64>(wreg, sWhi1, sWlo1, tid);
            __syncthreads();
            mma_half<4>(sHn, 136, 1, sWhi1, sWlo1, wm, wn, g, tg, acc3);
            float v = 0.0f;
#pragma unroll
            for (int mt = 0; mt < 2; mt++) {
#pragma unroll
                for (int nt = 0; nt < 4; nt++) {
                    int cc = wn * 32 + nt * 8 + tg * 2;
                    float2 bo = *(const float2*)(bo1 + cc);
                    float2 w2 = *(const float2*)(Wo2 + cc);
                    v += sspf(acc3[mt][nt][0] + bo.x) * w2.x + sspf(acc3[mt][nt][1] + bo.y) * w2.y;
                    v += sspf(acc3[mt][nt][2] + bo.x) * w2.x + sspf(acc3[mt][nt][3] + bo.y) * w2.y;
                }
            }
#pragma unroll
            for (int off = 16; off > 0; off >>= 1)
                v += __shfl_xor_sync(0xFFFFFFFFu, v, off);
            if (lane == 0) atomicAdd(&g_sum, v);
        }
    }
}

__global__ void final_kernel(float* __restrict__ out, const float* __restrict__ bo2) {
    float v = g_sum + (float)NN * bo2[0];
    out[0] = fmaxf(v, 0.0f);
}

// ---------------- launch ----------------
extern "C" void kernel_launch(void* const* d_in, const int* in_sizes, int n_in,
                              void* d_out, int out_size) {
    const int*   z    = (const int*)d_in[0];
    const float* pos  = (const float*)d_in[1];
    const int*   ei   = (const int*)d_in[2];
    const float* emb  = (const float*)d_in[3];
    const float* Wf1  = (const float*)d_in[4];
    const float* bf1  = (const float*)d_in[5];
    const float* Wf2  = (const float*)d_in[6];
    const float* bf2  = (const float*)d_in[7];
    const float* Wl1  = (const float*)d_in[8];
    const float* Wl2  = (const float*)d_in[9];
    const float* bl2  = (const float*)d_in[10];
    const float* Wl   = (const float*)d_in[11];
    const float* bl   = (const float*)d_in[12];
    const float* Wo1  = (const float*)d_in[13];
    const float* bo1  = (const float*)d_in[14];
    const float* Wo2  = (const float*)d_in[15];
    const float* bo2  = (const float*)d_in[16];
    float* out = (float*)d_out;

    __nv_bfloat16 *p_Hb, *p_Tb;
    cudaGetSymbolAddress((void**)&p_Hb, g_Hb);
    cudaGetSymbolAddress((void**)&p_Tb, g_Tb);

    const int FUSED_SMEM = (4 * 128 * 72 + 2 * 128 * 136) * (int)sizeof(__nv_bfloat16);
    cudaFuncSetAttribute(mega_kernel, cudaFuncAttributeMaxDynamicSharedMemorySize, FUSED_SMEM);

    // --- edge prep + dst sort ---
    zero_kernel<<<NN / 256, 256>>>();
    prep_kernel<<<EE / 256, 256>>>(pos, ei);
    scan_kernel<<<1, 1024>>>();
    scatter_kernel<<<EE / 256, 256>>>(ei);

    // --- filter tables (batched over all 6 interactions) ---
    tableH_kernel<<<dim3(NTAB / 8, NINTER), 128>>>(Wf1, bf1);
    gemm_filt<<<dim3(NTAB / 128, NINTER), 256>>>(
        p_Hb, Wf2, bf2, p_Tb,
        (size_t)NTAB * HID, (size_t)HID * HID, (size_t)HID, (size_t)NTAB * HID);

    // --- persistent fused network ---
    mega_kernel<<<NBLK, 256, FUSED_SMEM>>>(z, emb, Wl1, Wl2, bl2, Wl, bl, Wo1, bo1, Wo2);

    final_kernel<<<1, 1>>>(out, bo2);
}

// round 13
// speedup vs baseline: 1.3160x; 1.3160x over previous
#include <cuda_runtime.h>
#include <cuda_bf16.h>
#include <math.h>
#include <cstdint>

#define NN      16384
#define EE      262144
#define HID     128
#define NGAUSS  50
#define NINTER  6
#define NTAB    8192
#define DMAX    8.6610f
#define DELTA   (DMAX / (float)(NTAB - 1))
#define GSPACE  (10.0f / 49.0f)
#define GCOEFF  (-0.5f / (GSPACE * GSPACE))
#define LOG2F_C 0.69314718055994530942f
#define PI_O10  0.31415926535897932f

// ---------------- device scratch ----------------
__device__ float g_d[EE];
__device__ int   g_perm[EE];               // packed (t0 << 14) | src
__device__ int   g_start[NN + 1];
__device__ int   g_cnt[NN];
__device__ float g_h[NN * HID];            // fp32 residual stream
__device__ __nv_bfloat16 g_hb[NN * HID];   // bf16 shadow (first x GEMM)
__device__ __nv_bfloat16 g_xb[NN * HID];
__device__ __nv_bfloat16 g_aggb[NN * HID];
__device__ __nv_bfloat16 g_Tb[NINTER * NTAB * HID];
__device__ float g_sum;

__device__ __forceinline__ float sspf(float x) {
    float sp = (x > 15.0f) ? x : log1pf(expf(x));
    return sp - LOG2F_C;
}

// ---------------- prep kernels ----------------
__global__ void zero_kernel() {
    int i = blockIdx.x * blockDim.x + threadIdx.x;
    if (i < NN) g_cnt[i] = 0;
    if (i == 0) g_sum = 0.0f;
}

__global__ void prep_kernel(const float* __restrict__ pos, const int* __restrict__ ei) {
    int e = blockIdx.x * blockDim.x + threadIdx.x;
    if (e >= EE) return;
    int s = ei[e];
    int t = ei[EE + e];
    float dx = pos[3 * s + 0] - pos[3 * t + 0];
    float dy = pos[3 * s + 1] - pos[3 * t + 1];
    float dz = pos[3 * s + 2] - pos[3 * t + 2];
    g_d[e] = sqrtf(dx * dx + dy * dy + dz * dz);
    atomicAdd(&g_cnt[t], 1);
}

__global__ void scan_kernel() {
    __shared__ int part[1024];
    int tid = threadIdx.x;
    int base = tid * 16;
    int loc[16];
    int s = 0;
#pragma unroll
    for (int i = 0; i < 16; i++) { loc[i] = g_cnt[base + i]; s += loc[i]; }
    part[tid] = s;
    __syncthreads();
    for (int off = 1; off < 1024; off <<= 1) {
        int v = part[tid];
        int add = (tid >= off) ? part[tid - off] : 0;
        __syncthreads();
        part[tid] = v + add;
        __syncthreads();
    }
    int excl = (tid == 0) ? 0 : part[tid - 1];
#pragma unroll
    for (int i = 0; i < 16; i++) {
        g_start[base + i] = excl;
        g_cnt[base + i] = excl;
        excl += loc[i];
    }
    if (tid == 1023) g_start[NN] = excl;
}

__global__ void scatter_kernel(const int* __restrict__ ei) {
    int e = blockIdx.x * blockDim.x + threadIdx.x;
    if (e >= EE) return;
    int t = ei[EE + e];
    int s = ei[e];
    float f = g_d[e] * (1.0f / DELTA);
    int t0 = (int)(f + 0.5f);              // nearest table entry
    t0 = min(t0, NTAB - 1);
    int p = atomicAdd(&g_cnt[t], 1);
    g_perm[p] = (t0 << 14) | s;
}

__global__ void emb_kernel(const int* __restrict__ z, const float* __restrict__ emb) {
    int idx = blockIdx.x * blockDim.x + threadIdx.x;
    if (idx >= NN * HID) return;
    int n = idx >> 7, c = idx & 127;
    float v = emb[z[n] * HID + c];
    g_h[idx] = v;
    g_hb[idx] = __float2bfloat16(v);
}

// ---------------- MMA helpers ----------------
#define MMA16816(d, a, b0, b1) \
    asm volatile("mma.sync.aligned.m16n8k16.row.col.f32.bf16.bf16.f32 " \
        "{%0,%1,%2,%3}, {%4,%5,%6,%7}, {%8,%9}, {%0,%1,%2,%3};" \
        : "+f"((d)[0]), "+f"((d)[1]), "+f"((d)[2]), "+f"((d)[3]) \
        : "r"((a)[0]), "r"((a)[1]), "r"((a)[2]), "r"((a)[3]), "r"(b0), "r"(b1))

// ---------------- pipelined weight staging helpers ----------------
template <int NC>
__device__ __forceinline__ void ldg_chunk(const float* __restrict__ W, int kh,
                                          float* wreg, int tid) {
#pragma unroll
    for (int i = 0; i < 64 * NC / 256; i++) {
        int flat = tid + i * 256;
        int kp = flat / NC, n = flat % NC;
        wreg[i] = W[(size_t)(kh * 64 + kp) * NC + n];
    }
}
// Wf1 chunk: rows 0..49 valid, 50..63 zero-padded
__device__ __forceinline__ void ldg_chunk_f1(const float* __restrict__ W,
                                             float* wreg, int tid) {
#pragma unroll
    for (int i = 0; i < 32; i++) {
        int flat = tid + i * 256;
        int kp = flat >> 7, n = flat & 127;
        wreg[i] = (kp < NGAUSS) ? W[kp * 128 + n] : 0.0f;
    }
}
template <int NC>
__device__ __forceinline__ void sts_chunk(const float* wreg,
                                          __nv_bfloat16* hi, __nv_bfloat16* lo, int tid) {
#pragma unroll
    for (int i = 0; i < 64 * NC / 256; i++) {
        int flat = tid + i * 256;
        int kp = flat / NC, n = flat % NC;
        float v = wreg[i];
        __nv_bfloat16 h = __float2bfloat16(v);
        hi[n * 72 + kp] = h;
        lo[n * 72 + kp] = __float2bfloat16(v - __bfloat162float(h));
    }
}

template <int NT>
__device__ __forceinline__ void mma_half(
    const __nv_bfloat16* __restrict__ A, int lda, int kh,
    const __nv_bfloat16* hi, const __nv_bfloat16* lo,
    int wm, int wn, int g, int tg, float acc[2][NT][4])
{
    const __nv_bfloat16* rp0 = A + (wm * 32 + g) * lda;
    const int colbase = wn * (NT * 8);
#pragma unroll
    for (int ks = 0; ks < 4; ks++) {
        int kc = kh * 64 + ks * 16 + tg * 2;
        uint32_t af[2][4];
#pragma unroll
        for (int mt = 0; mt < 2; mt++) {
            const __nv_bfloat16* rp = rp0 + mt * 16 * lda;
            af[mt][0] = *(const uint32_t*)(rp + kc);
            af[mt][1] = *(const uint32_t*)(rp + 8 * lda + kc);
            af[mt][2] = *(const uint32_t*)(rp + kc + 8);
            af[mt][3] = *(const uint32_t*)(rp + 8 * lda + kc + 8);
        }
        int c = ks * 16 + tg * 2;
#pragma unroll
        for (int nt = 0; nt < NT; nt++) {
            int n = colbase + nt * 8 + g;
            uint32_t bh0 = *(const uint32_t*)(hi + n * 72 + c);
            uint32_t bh1 = *(const uint32_t*)(hi + n * 72 + c + 8);
            uint32_t bl0 = *(const uint32_t*)(lo + n * 72 + c);
            uint32_t bl1 = *(const uint32_t*)(lo + n * 72 + c + 8);
#pragma unroll
            for (int mt = 0; mt < 2; mt++) {
                MMA16816(acc[mt][nt], af[mt], bh0, bh1);
                MMA16816(acc[mt][nt], af[mt], bl0, bl1);
            }
        }
    }
}

// ---------------- filter-table builder: ea->GEMM->ssp->GEMM->cutoff, all MMA ----------------
__global__ __launch_bounds__(256) void tableT_kernel(
    const float* __restrict__ Wf1, const float* __restrict__ bf1,
    const float* __restrict__ Wf2, const float* __restrict__ bf2)
{
    extern __shared__ __align__(16) char smem_raw[];
    __nv_bfloat16* sWhi0 = (__nv_bfloat16*)smem_raw;     // 128*72
    __nv_bfloat16* sWlo0 = sWhi0 + 128 * 72;
    __nv_bfloat16* sWhi1 = sWlo0 + 128 * 72;
    __nv_bfloat16* sWlo1 = sWhi1 + 128 * 72;
    __nv_bfloat16* sEa   = sWlo1 + 128 * 72;             // 128*72 (K=64 padded)
    __nv_bfloat16* sT    = sEa + 128 * 72;               // 128*136

    const int tid = threadIdx.x;
    const int w = tid >> 5, lane = tid & 31;
    const int wm = w >> 1, wn = w & 1;
    const int g = lane >> 2, tg = lane & 3;
    const int inter = blockIdx.y;
    const int row0 = blockIdx.x * 128;

    const float* W1 = Wf1 + (size_t)inter * NGAUSS * HID;
    const float* W2 = Wf2 + (size_t)inter * HID * HID;
    const float* b1 = bf1 + (size_t)inter * HID;
    const float* b2 = bf2 + (size_t)inter * HID;

    // Gaussian rows (bf16, K padded to 64)
    for (int idx = tid; idx < 128 * 64; idx += 256) {
        int r = idx >> 6, k = idx & 63;
        float v = 0.0f;
        if (k < NGAUSS) {
            float u = (float)(row0 + r) * DELTA - (float)k * GSPACE;
            v = expf(GCOEFF * u * u);
        }
        sEa[r * 72 + k] = __float2bfloat16(v);
    }

    float wreg[32];
    ldg_chunk_f1(W1, wreg, tid);
    sts_chunk<128>(wreg, sWhi0, sWlo0, tid);
    __syncthreads();

    // ---- GEMM1: H = ssp(ea @ Wf1 + bf1) -> sT ----
    {
        float acc1[2][8][4] = {};
        ldg_chunk<128>(W2, 0, wreg, tid);
        mma_half<8>(sEa, 72, 0, sWhi0, sWlo0, wm, wn, g, tg, acc1);
        sts_chunk<128>(wreg, sWhi1, sWlo1, tid);
#pragma unroll
        for (int mt = 0; mt < 2; mt++) {
            int r0 = wm * 32 + mt * 16 + g;
            int r1 = r0 + 8;
#pragma unroll
            for (int nt = 0; nt < 8; nt++) {
                int cc = wn * 64 + nt * 8 + tg * 2;
                float2 bv = *(const float2*)(b1 + cc);
                float vx0 = sspf(acc1[mt][nt][0] + bv.x);
                float vy0 = sspf(acc1[mt][nt][1] + bv.y);
                float vx1 = sspf(acc1[mt][nt][2] + bv.x);
                float vy1 = sspf(acc1[mt][nt][3] + bv.y);
                *(__nv_bfloat162*)(sT + r0 * 136 + cc) = __floats2bfloat162_rn(vx0, vy0);
                *(__nv_bfloat162*)(sT + r1 * 136 + cc) = __floats2bfloat162_rn(vx1, vy1);
            }
        }
    }
    __syncthreads();

    // ---- GEMM2: T = (H @ Wf2 + bf2) * cutoff(row) -> g_Tb ----
    {
        float acc2[2][8][4] = {};
        ldg_chunk<128>(W2, 1, wreg, tid);
        mma_half<8>(sT, 136, 0, sWhi1, sWlo1, wm, wn, g, tg, acc2);
        sts_chunk<128>(wreg, sWhi0, sWlo0, tid);
        __syncthreads();
        mma_half<8>(sT, 136, 1, sWhi0, sWlo0, wm, wn, g, tg, acc2);
        __nv_bfloat16* outB = g_Tb + (size_t)inter * NTAB * HID;
#pragma unroll
        for (int mt = 0; mt < 2; mt++) {
            int r0 = row0 + wm * 32 + mt * 16 + g;
            int r1 = r0 + 8;
            float s0 = 0.5f * (cosf((float)r0 * DELTA * PI_O10) + 1.0f);
            float s1 = 0.5f * (cosf((float)r1 * DELTA * PI_O10) + 1.0f);
#pragma unroll
            for (int nt = 0; nt < 8; nt++) {
                int cc = wn * 64 + nt * 8 + tg * 2;
                float2 bv = *(const float2*)(b2 + cc);
                float vx0 = (acc2[mt][nt][0] + bv.x) * s0;
                float vy0 = (acc2[mt][nt][1] + bv.y) * s0;
                float vx1 = (acc2[mt][nt][2] + bv.x) * s1;
                float vy1 = (acc2[mt][nt][3] + bv.y) * s1;
                *(__nv_bfloat162*)(outB + (size_t)r0 * 128 + cc) = __floats2bfloat162_rn(vx0, vy0);
                *(__nv_bfloat162*)(outB + (size_t)r1 * 128 + cc) = __floats2bfloat162_rn(vx1, vy1);
            }
        }
    }
}

// ---------------- standalone GEMM: x0 = hb @ Wl1[0] ----------------
__global__ __launch_bounds__(256) void gemm_x0(
    const __nv_bfloat16* __restrict__ A, const float* __restrict__ W,
    __nv_bfloat16* __restrict__ outB)
{
    __shared__ __nv_bfloat16 sBhi[128 * 72];
    __shared__ __nv_bfloat16 sBlo[128 * 72];

    const int tid = threadIdx.x;
    const int w = tid >> 5, lane = tid & 31;
    const int wm = w >> 1, wn = w & 1;
    const int g = lane >> 2, tg = lane & 3;
    const int row0 = blockIdx.x * 128;

    float acc[2][8][4] = {};
    const __nv_bfloat16* aBase = A + (size_t)row0 * 128;
    float wreg[32];

    ldg_chunk<128>(W, 0, wreg, tid);
    sts_chunk<128>(wreg, sBhi, sBlo, tid);
    __syncthreads();
    ldg_chunk<128>(W, 1, wreg, tid);
    mma_half<8>(aBase, 128, 0, sBhi, sBlo, wm, wn, g, tg, acc);
    __syncthreads();
    sts_chunk<128>(wreg, sBhi, sBlo, tid);
    __syncthreads();
    mma_half<8>(aBase, 128, 1, sBhi, sBlo, wm, wn, g, tg, acc);

#pragma unroll
    for (int mt = 0; mt < 2; mt++) {
        int r0 = row0 + wm * 32 + mt * 16 + g;
        int r1 = r0 + 8;
#pragma unroll
        for (int nt = 0; nt < 8; nt++) {
            int cc = wn * 64 + nt * 8 + tg * 2;
            *(__nv_bfloat162*)(outB + (size_t)r0 * 128 + cc) =
                __floats2bfloat162_rn(acc[mt][nt][0], acc[mt][nt][1]);
            *(__nv_bfloat162*)(outB + (size_t)r1 * 128 + cc) =
                __floats2bfloat162_rn(acc[mt][nt][2], acc[mt][nt][3]);
        }
    }
}

// ---------------- fused interaction update: 3 chained GEMMs, pipelined weights ----------------
template <bool LAST>
__global__ __launch_bounds__(256) void fused_update(
    const __nv_bfloat16* __restrict__ aggb,
    float* __restrict__ h,
    const float* __restrict__ Wl2, const float* __restrict__ bl2,
    const float* __restrict__ Wl,  const float* __restrict__ bl,
    const float* __restrict__ W3,
    const float* __restrict__ bo1, const float* __restrict__ Wo2,
    __nv_bfloat16* __restrict__ xb)
{
    extern __shared__ __align__(16) char smem_raw[];
    __nv_bfloat16* sWhi0 = (__nv_bfloat16*)smem_raw;     // 128*72
    __nv_bfloat16* sWlo0 = sWhi0 + 128 * 72;
    __nv_bfloat16* sWhi1 = sWlo0 + 128 * 72;
    __nv_bfloat16* sWlo1 = sWhi1 + 128 * 72;
    __nv_bfloat16* sT    = sWlo1 + 128 * 72;             // 128*136
    __nv_bfloat16* sHn   = sT + 128 * 136;               // 128*136

    const int tid = threadIdx.x;
    const int w = tid >> 5, lane = tid & 31;
    const int wm = w >> 1, wn = w & 1;
    const int g = lane >> 2, tg = lane & 3;
    const int row0 = blockIdx.x * 128;

    float wreg[32];
    const __nv_bfloat16* aggA = aggb + (size_t)row0 * 128;

    // preload (Wl2, kh0)
    ldg_chunk<128>(Wl2, 0, wreg, tid);
    sts_chunk<128>(wreg, sWhi0, sWlo0, tid);
    __syncthreads();

    // ======== stage 1: t = ssp(aggb @ Wl2 + bl2) ========
    float acc1[2][8][4] = {};
    ldg_chunk<128>(Wl2, 1, wreg, tid);
    mma_half<8>(aggA, 128, 0, sWhi0, sWlo0, wm, wn, g, tg, acc1);
    sts_chunk<128>(wreg, sWhi1, sWlo1, tid);
    __syncthreads();

    ldg_chunk<128>(Wl, 0, wreg, tid);
    mma_half<8>(aggA, 128, 1, sWhi1, sWlo1, wm, wn, g, tg, acc1);
    sts_chunk<128>(wreg, sWhi0, sWlo0, tid);
    {
#pragma unroll
        for (int mt = 0; mt < 2; mt++) {
            int r0 = wm * 32 + mt * 16 + g;
            int r1 = r0 + 8;
#pragma unroll
            for (int nt = 0; nt < 8; nt++) {
                int cc = wn * 64 + nt * 8 + tg * 2;
                float2 bv = *(const float2*)(bl2 + cc);
                float vx0 = sspf(acc1[mt][nt][0] + bv.x);
                float vy0 = sspf(acc1[mt][nt][1] + bv.y);
                float vx1 = sspf(acc1[mt][nt][2] + bv.x);
                float vy1 = sspf(acc1[mt][nt][3] + bv.y);
                *(__nv_bfloat162*)(sT + r0 * 136 + cc) = __floats2bfloat162_rn(vx0, vy0);
                *(__nv_bfloat162*)(sT + r1 * 136 + cc) = __floats2bfloat162_rn(vx1, vy1);
            }
        }
    }
    __syncthreads();

    // ======== stage 2: hn = t @ Wl + bl + h ========
    float acc2[2][8][4] = {};
    ldg_chunk<128>(Wl, 1, wreg, tid);
    mma_half<8>(sT, 136, 0, sWhi0, sWlo0, wm, wn, g, tg, acc2);
    sts_chunk<128>(wreg, sWhi1, sWlo1, tid);
    __syncthreads();

    if (!LAST) ldg_chunk<128>(W3, 0, wreg, tid);
    else       ldg_chunk<64>(W3, 0, wreg, tid);
    mma_half<8>(sT, 136, 1, sWhi1, sWlo1, wm, wn, g, tg, acc2);
    if (!LAST) sts_chunk<128>(wreg, sWhi0, sWlo0, tid);
    else       sts_chunk<64>(wreg, sWhi0, sWlo0, tid);
    {
#pragma unroll
        for (int mt = 0; mt < 2; mt++) {
            int r0 = wm * 32 + mt * 16 + g;
            int r1 = r0 + 8;
            float* h0p = h + (size_t)(row0 + r0) * 128;
            float* h1p = h + (size_t)(row0 + r1) * 128;
#pragma unroll
            for (int nt = 0; nt < 8; nt++) {
                int cc = wn * 64 + nt * 8 + tg * 2;
                float2 bv = *(const float2*)(bl + cc);
                float2 e0 = *(const float2*)(h0p + cc);
                float2 e1 = *(const float2*)(h1p + cc);
                float vx0 = acc2[mt][nt][0] + bv.x + e0.x;
                float vy0 = acc2[mt][nt][1] + bv.y + e0.y;
                float vx1 = acc2[mt][nt][2] + bv.x + e1.x;
                float vy1 = acc2[mt][nt][3] + bv.y + e1.y;
                *(float2*)(h0p + cc) = make_float2(vx0, vy0);
                *(float2*)(h1p + cc) = make_float2(vx1, vy1);
                *(__nv_bfloat162*)(sHn + r0 * 136 + cc) = __floats2bfloat162_rn(vx0, vy0);
                *(__nv_bfloat162*)(sHn + r1 * 136 + cc) = __floats2bfloat162_rn(vx1, vy1);
            }
        }
    }
    __syncthreads();

    // ======== stage 3: next x or readout ========
    if (!LAST) {
        float acc3[2][8][4] = {};
        ldg_chunk<128>(W3, 1, wreg, tid);
        mma_half<8>(sHn, 136, 0, sWhi0, sWlo0, wm, wn, g, tg, acc3);
        sts_chunk<128>(wreg, sWhi1, sWlo1, tid);
        __syncthreads();
        mma_half<8>(sHn, 136, 1, sWhi1, sWlo1, wm, wn, g, tg, acc3);
#pragma unroll
        for (int mt = 0; mt < 2; mt++) {
            int r0 = row0 + wm * 32 + mt * 16 + g;
            int r1 = r0 + 8;
#pragma unroll
            for (int nt = 0; nt < 8; nt++) {
                int cc = wn * 64 + nt * 8 + tg * 2;
                *(__nv_bfloat162*)(xb + (size_t)r0 * 128 + cc) =
                    __floats2bfloat162_rn(acc3[mt][nt][0], acc3[mt][nt][1]);
                *(__nv_bfloat162*)(xb + (size_t)r1 * 128 + cc) =
                    __floats2bfloat162_rn(acc3[mt][nt][2], acc3[mt][nt][3]);
            }
        }
    } else {
        float acc3[2][4][4] = {};
        ldg_chunk<64>(W3, 1, wreg, tid);
        mma_half<4>(sHn, 136, 0, sWhi0, sWlo0, wm, wn, g, tg, acc3);
        sts_chunk<64>(wreg, sWhi1, sWlo1, tid);
        __syncthreads();
        mma_half<4>(sHn, 136, 1, sWhi1, sWlo1, wm, wn, g, tg, acc3);
        float v = 0.0f;
#pragma unroll
        for (int mt = 0; mt < 2; mt++) {
#pragma unroll
            for (int nt = 0; nt < 4; nt++) {
                int cc = wn * 32 + nt * 8 + tg * 2;
                float2 bo = *(const float2*)(bo1 + cc);
                float2 w2 = *(const float2*)(Wo2 + cc);
                v += sspf(acc3[mt][nt][0] + bo.x) * w2.x + sspf(acc3[mt][nt][1] + bo.y) * w2.y;
                v += sspf(acc3[mt][nt][2] + bo.x) * w2.x + sspf(acc3[mt][nt][3] + bo.y) * w2.y;
            }
        }
#pragma unroll
        for (int off = 16; off > 0; off >>= 1)
            v += __shfl_xor_sync(0xFFFFFFFFu, v, off);
        if (lane == 0) atomicAdd(&g_sum, v);
    }
}

// ---------------- edge aggregation (dst-sorted, warp/node, nearest table) ----------------
__device__ __forceinline__ void edge_acc(const __nv_bfloat16* xb, const __nv_bfloat16* Tb,
                                         int pk, int lane, float4& acc) {
    int s = pk & 16383;
    int t0 = pk >> 14;
    uint2 xv = ((const uint2*)(xb + (size_t)s * 128))[lane];
    uint2 tv = ((const uint2*)(Tb + (size_t)t0 * 128))[lane];
    float2 x0 = __bfloat1622float2(*(__nv_bfloat162*)&xv.x);
    float2 x1 = __bfloat1622float2(*(__nv_bfloat162*)&xv.y);
    float2 f0 = __bfloat1622float2(*(__nv_bfloat162*)&tv.x);
    float2 f1 = __bfloat1622float2(*(__nv_bfloat162*)&tv.y);
    acc.x += x0.x * f0.x;
    acc.y += x0.y * f0.y;
    acc.z += x1.x * f1.x;
    acc.w += x1.y * f1.y;
}

__global__ void agg_kernel(const __nv_bfloat16* __restrict__ xb,
                           const __nv_bfloat16* __restrict__ Tb) {
    int warp = (blockIdx.x * blockDim.x + threadIdx.x) >> 5;
    int lane = threadIdx.x & 31;
    if (warp >= NN) return;
    int b = g_start[warp];
    int e = g_start[warp + 1];
    float4 acc = make_float4(0.f, 0.f, 0.f, 0.f);
    int j = b;
    for (; j + 4 <= e; j += 4) {
        int pk0 = g_perm[j],     pk1 = g_perm[j + 1];
        int pk2 = g_perm[j + 2], pk3 = g_perm[j + 3];
        edge_acc(xb, Tb, pk0, lane, acc);
        edge_acc(xb, Tb, pk1, lane, acc);
        edge_acc(xb, Tb, pk2, lane, acc);
        edge_acc(xb, Tb, pk3, lane, acc);
    }
    for (; j < e; j++) edge_acc(xb, Tb, g_perm[j], lane, acc);
    __nv_bfloat162 o0 = __floats2bfloat162_rn(acc.x, acc.y);
    __nv_bfloat162 o1 = __floats2bfloat162_rn(acc.z, acc.w);
    uint2 ov;
    ov.x = *(uint32_t*)&o0;
    ov.y = *(uint32_t*)&o1;
    ((uint2*)(g_aggb + (size_t)warp * 128))[lane] = ov;
}

__global__ void final_kernel(float* __restrict__ out, const float* __restrict__ bo2) {
    float v = g_sum + (float)NN * bo2[0];
    out[0] = fmaxf(v, 0.0f);
}

// ---------------- launch ----------------
extern "C" void kernel_launch(void* const* d_in, const int* in_sizes, int n_in,
                              void* d_out, int out_size) {
    const int*   z    = (const int*)d_in[0];
    const float* pos  = (const float*)d_in[1];
    const int*   ei   = (const int*)d_in[2];
    const float* emb  = (const float*)d_in[3];
    const float* Wf1  = (const float*)d_in[4];
    const float* bf1  = (const float*)d_in[5];
    const float* Wf2  = (const float*)d_in[6];
    const float* bf2  = (const float*)d_in[7];
    const float* Wl1  = (const float*)d_in[8];
    const float* Wl2  = (const float*)d_in[9];
    const float* bl2  = (const float*)d_in[10];
    const float* Wl   = (const float*)d_in[11];
    const float* bl   = (const float*)d_in[12];
    const float* Wo1  = (const float*)d_in[13];
    const float* bo1  = (const float*)d_in[14];
    const float* Wo2  = (const float*)d_in[15];
    const float* bo2  = (const float*)d_in[16];
    float* out = (float*)d_out;

    float *p_h;
    __nv_bfloat16 *p_hb, *p_xb, *p_aggb, *p_Tb;
    cudaGetSymbolAddress((void**)&p_h,    g_h);
    cudaGetSymbolAddress((void**)&p_hb,   g_hb);
    cudaGetSymbolAddress((void**)&p_xb,   g_xb);
    cudaGetSymbolAddress((void**)&p_aggb, g_aggb);
    cudaGetSymbolAddress((void**)&p_Tb,   g_Tb);

    const int FUSED_SMEM = (4 * 128 * 72 + 2 * 128 * 136) * (int)sizeof(__nv_bfloat16);
    const int TABLE_SMEM = (5 * 128 * 72 + 128 * 136) * (int)sizeof(__nv_bfloat16);
    cudaFuncSetAttribute(fused_update<false>, cudaFuncAttributeMaxDynamicSharedMemorySize, FUSED_SMEM);
    cudaFuncSetAttribute(fused_update<true>,  cudaFuncAttributeMaxDynamicSharedMemorySize, FUSED_SMEM);
    cudaFuncSetAttribute(tableT_kernel, cudaFuncAttributeMaxDynamicSharedMemorySize, TABLE_SMEM);

    // --- edge prep + dst sort ---
    zero_kernel<<<NN / 256, 256>>>();
    prep_kernel<<<EE / 256, 256>>>(pos, ei);
    scan_kernel<<<1, 1024>>>();
    scatter_kernel<<<EE / 256, 256>>>(ei);
    emb_kernel<<<NN * HID / 256, 256>>>(z, emb);

    // --- filter tables, all-MMA (batched over 6 interactions) ---
    tableT_kernel<<<dim3(NTAB / 128, NINTER), 256, TABLE_SMEM>>>(Wf1, bf1, Wf2, bf2);

    // --- first x = h @ Wl1[0] ---
    gemm_x0<<<NN / 128, 256>>>(p_hb, Wl1, p_xb);

    // --- interaction blocks: agg + fused pipelined update ---
    for (int i = 0; i < NINTER; i++) {
        agg_kernel<<<NN / 8, 256>>>(p_xb, p_Tb + (size_t)i * NTAB * HID);
        if (i < NINTER - 1) {
            fused_update<false><<<NN / 128, 256, FUSED_SMEM>>>(
                p_aggb, p_h,
                Wl2 + (size_t)i * HID * HID, bl2 + (size_t)i * HID,
                Wl  + (size_t)i * HID * HID, bl  + (size_t)i * HID,
                Wl1 + (size_t)(i + 1) * HID * HID, nullptr, nullptr, p_xb);
        } else {
            fused_update<true><<<NN / 128, 256, FUSED_SMEM>>>(
                p_aggb, p_h,
                Wl2 + (size_t)i * HID * HID, bl2 + (size_t)i * HID,
                Wl  + (size_t)i * HID * HID, bl  + (size_t)i * HID,
                Wo1, bo1, Wo2, nullptr);
        }
    }

    final_kernel<<<1, 1>>>(out, bo2);
}

// round 14
// speedup vs baseline: 1.4524x; 1.1036x over previous
#include <cuda_runtime.h>
#include <cuda_bf16.h>
#include <math.h>
#include <cstdint>

#define NN      16384
#define EE      262144
#define HID     128
#define NGAUSS  50
#define NINTER  6
#define NTAB    8192
#define DMAX    8.6610f
#define DELTA   (DMAX / (float)(NTAB - 1))
#define GSPACE  (10.0f / 49.0f)
#define GCOEFF  (-0.5f / (GSPACE * GSPACE))
#define LOG2F_C 0.69314718055994530942f
#define PI_O10  0.31415926535897932f

#define SLOT_ELEMS 18432   // one 64x128 chunk: hi[128*72] + lo[128*72] bf16
#define NSLOT 56

// ---------------- device scratch ----------------
__device__ float g_d[EE];
__device__ int   g_perm[EE];               // packed (t0 << 14) | src
__device__ int   g_start[NN + 1];
__device__ int   g_cnt[NN];
__device__ float g_h[NN * HID];            // fp32 residual stream
__device__ __nv_bfloat16 g_hb[NN * HID];   // bf16 shadow (first x GEMM)
__device__ __nv_bfloat16 g_xb[NN * HID];
__device__ __nv_bfloat16 g_aggb[NN * HID];
__device__ __nv_bfloat16 g_Tb[NINTER * NTAB * HID];
__device__ __nv_bfloat16 g_Wc[NSLOT * SLOT_ELEMS];   // preconverted weights
__device__ float g_sum;

__device__ __forceinline__ float sspf(float x) {
    float sp = (x > 15.0f) ? x : log1pf(expf(x));
    return sp - LOG2F_C;
}

// ---------------- prep kernels ----------------
__global__ void zero_kernel() {
    int i = blockIdx.x * blockDim.x + threadIdx.x;
    if (i < NN) g_cnt[i] = 0;
    if (i == 0) g_sum = 0.0f;
}

__global__ void prep_kernel(const float* __restrict__ pos, const int* __restrict__ ei) {
    int e = blockIdx.x * blockDim.x + threadIdx.x;
    if (e >= EE) return;
    int s = ei[e];
    int t = ei[EE + e];
    float dx = pos[3 * s + 0] - pos[3 * t + 0];
    float dy = pos[3 * s + 1] - pos[3 * t + 1];
    float dz = pos[3 * s + 2] - pos[3 * t + 2];
    g_d[e] = sqrtf(dx * dx + dy * dy + dz * dz);
    atomicAdd(&g_cnt[t], 1);
}

__global__ void scan_kernel() {
    __shared__ int part[1024];
    int tid = threadIdx.x;
    int base = tid * 16;
    int loc[16];
    int s = 0;
#pragma unroll
    for (int i = 0; i < 16; i++) { loc[i] = g_cnt[base + i]; s += loc[i]; }
    part[tid] = s;
    __syncthreads();
    for (int off = 1; off < 1024; off <<= 1) {
        int v = part[tid];
        int add = (tid >= off) ? part[tid - off] : 0;
        __syncthreads();
        part[tid] = v + add;
        __syncthreads();
    }
    int excl = (tid == 0) ? 0 : part[tid - 1];
#pragma unroll
    for (int i = 0; i < 16; i++) {
        g_start[base + i] = excl;
        g_cnt[base + i] = excl;
        excl += loc[i];
    }
    if (tid == 1023) g_start[NN] = excl;
}

__global__ void scatter_kernel(const int* __restrict__ ei) {
    int e = blockIdx.x * blockDim.x + threadIdx.x;
    if (e >= EE) return;
    int t = ei[EE + e];
    int s = ei[e];
    float f = g_d[e] * (1.0f / DELTA);
    int t0 = (int)(f + 0.5f);              // nearest table entry
    t0 = min(t0, NTAB - 1);
    int p = atomicAdd(&g_cnt[t], 1);
    g_perm[p] = (t0 << 14) | s;
}

__global__ void emb_kernel(const int* __restrict__ z, const float* __restrict__ emb) {
    int idx = blockIdx.x * blockDim.x + threadIdx.x;
    if (idx >= NN * HID) return;
    int n = idx >> 7, c = idx & 127;
    float v = emb[z[n] * HID + c];
    g_h[idx] = v;
    g_hb[idx] = __float2bfloat16(v);
}

// ---------------- weight preconversion: fp32 -> hi/lo bf16 in fragment layout ----------------
// slot map: 0..11 Wl2[i](kh), 12..23 Wl[i](kh), 24..35 Wl1[i](kh),
//           36..37 Wo1(kh, NC=64), 38..43 Wf1[i](padded K), 44..55 Wf2[i](kh)
__global__ void convW_kernel(const float* __restrict__ Wl2, const float* __restrict__ Wl,
                             const float* __restrict__ Wl1, const float* __restrict__ Wo1,
                             const float* __restrict__ Wf1, const float* __restrict__ Wf2) {
    int slot = blockIdx.x;
    int tid = threadIdx.x;
    __nv_bfloat16* dst = g_Wc + (size_t)slot * SLOT_ELEMS;
    const float* src;
    int kh, NC = 128;
    bool padK = false;
    if (slot < 12)      { src = Wl2 + (size_t)(slot >> 1) * 16384; kh = slot & 1; }
    else if (slot < 24) { src = Wl  + (size_t)((slot - 12) >> 1) * 16384; kh = slot & 1; }
    else if (slot < 36) { src = Wl1 + (size_t)((slot - 24) >> 1) * 16384; kh = slot & 1; }
    else if (slot < 38) { src = Wo1; kh = slot - 36; NC = 64; }
    else if (slot < 44) { src = Wf1 + (size_t)(slot - 38) * NGAUSS * 128; kh = 0; padK = true; }
    else                { src = Wf2 + (size_t)((slot - 44) >> 1) * 16384; kh = slot & 1; }

    for (int flat = tid; flat < 128 * 64; flat += 256) {
        int n = flat >> 6, kp = flat & 63;
        int krow = kh * 64 + kp;
        float v = 0.0f;
        if (n < NC && !(padK && krow >= NGAUSS))
            v = src[(size_t)krow * NC + n];
        __nv_bfloat16 h = __float2bfloat16(v);
        dst[n * 72 + kp] = h;
        dst[9216 + n * 72 + kp] = __float2bfloat16(v - __bfloat162float(h));
    }
}

// ---------------- MMA helpers ----------------
#define MMA16816(d, a, b0, b1) \
    asm volatile("mma.sync.aligned.m16n8k16.row.col.f32.bf16.bf16.f32 " \
        "{%0,%1,%2,%3}, {%4,%5,%6,%7}, {%8,%9}, {%0,%1,%2,%3};" \
        : "+f"((d)[0]), "+f"((d)[1]), "+f"((d)[2]), "+f"((d)[3]) \
        : "r"((a)[0]), "r"((a)[1]), "r"((a)[2]), "r"((a)[3]), "r"(b0), "r"(b1))

// ---------------- preconverted-weight staging (pure copy) ----------------
__device__ __forceinline__ void ldg_w(const __nv_bfloat16* __restrict__ src,
                                      uint4* wreg, int tid) {
    const uint4* s = (const uint4*)src;
#pragma unroll
    for (int i = 0; i < 9; i++) wreg[i] = s[tid + i * 256];
}
__device__ __forceinline__ void sts_w(const uint4* wreg, __nv_bfloat16* dsthi, int tid) {
    uint4* d = (uint4*)dsthi;
#pragma unroll
    for (int i = 0; i < 9; i++) d[tid + i * 256] = wreg[i];
}

template <int NT>
__device__ __forceinline__ void mma_half(
    const __nv_bfloat16* __restrict__ A, int lda, int kh,
    const __nv_bfloat16* hi, const __nv_bfloat16* lo,
    int wm, int wn, int g, int tg, float acc[2][NT][4])
{
    const __nv_bfloat16* rp0 = A + (wm * 32 + g) * lda;
    const int colbase = wn * (NT * 8);
#pragma unroll
    for (int ks = 0; ks < 4; ks++) {
        int kc = kh * 64 + ks * 16 + tg * 2;
        uint32_t af[2][4];
#pragma unroll
        for (int mt = 0; mt < 2; mt++) {
            const __nv_bfloat16* rp = rp0 + mt * 16 * lda;
            af[mt][0] = *(const uint32_t*)(rp + kc);
            af[mt][1] = *(const uint32_t*)(rp + 8 * lda + kc);
            af[mt][2] = *(const uint32_t*)(rp + kc + 8);
            af[mt][3] = *(const uint32_t*)(rp + 8 * lda + kc + 8);
        }
        int c = ks * 16 + tg * 2;
#pragma unroll
        for (int nt = 0; nt < NT; nt++) {
            int n = colbase + nt * 8 + g;
            uint32_t bh0 = *(const uint32_t*)(hi + n * 72 + c);
            uint32_t bh1 = *(const uint32_t*)(hi + n * 72 + c + 8);
            uint32_t bl0 = *(const uint32_t*)(lo + n * 72 + c);
            uint32_t bl1 = *(const uint32_t*)(lo + n * 72 + c + 8);
#pragma unroll
            for (int mt = 0; mt < 2; mt++) {
                MMA16816(acc[mt][nt], af[mt], bh0, bh1);
                MMA16816(acc[mt][nt], af[mt], bl0, bl1);
            }
        }
    }
}

// ---------------- filter-table builder: ea->GEMM->ssp->GEMM->cutoff ----------------
__global__ __launch_bounds__(256) void tableT_kernel(
    const float* __restrict__ bf1, const float* __restrict__ bf2)
{
    extern __shared__ __align__(16) char smem_raw[];
    __nv_bfloat16* sWhi0 = (__nv_bfloat16*)smem_raw;     // 128*72
    __nv_bfloat16* sWlo0 = sWhi0 + 128 * 72;
    __nv_bfloat16* sWhi1 = sWlo0 + 128 * 72;
    __nv_bfloat16* sWlo1 = sWhi1 + 128 * 72;
    __nv_bfloat16* sEa   = sWlo1 + 128 * 72;             // 128*72 (K=64 padded)
    __nv_bfloat16* sT    = sEa + 128 * 72;               // 128*136

    const int tid = threadIdx.x;
    const int w = tid >> 5, lane = tid & 31;
    const int wm = w >> 1, wn = w & 1;
    const int g = lane >> 2, tg = lane & 3;
    const int inter = blockIdx.y;
    const int row0 = blockIdx.x * 128;

    const __nv_bfloat16* cWf1 = g_Wc + (size_t)(38 + inter) * SLOT_ELEMS;
    const __nv_bfloat16* cWf2 = g_Wc + (size_t)(44 + 2 * inter) * SLOT_ELEMS;
    const float* b1 = bf1 + (size_t)inter * HID;
    const float* b2 = bf2 + (size_t)inter * HID;

    // Gaussian rows (bf16, K padded to 64)
    for (int idx = tid; idx < 128 * 64; idx += 256) {
        int r = idx >> 6, k = idx & 63;
        float v = 0.0f;
        if (k < NGAUSS) {
            float u = (float)(row0 + r) * DELTA - (float)k * GSPACE;
            v = expf(GCOEFF * u * u);
        }
        sEa[r * 72 + k] = __float2bfloat16(v);
    }

    uint4 wreg[9];
    ldg_w(cWf1, wreg, tid);
    sts_w(wreg, sWhi0, tid);
    __syncthreads();

    // ---- GEMM1: H = ssp(ea @ Wf1 + bf1) -> sT ----
    {
        float acc1[2][8][4] = {};
        ldg_w(cWf2, wreg, tid);
        mma_half<8>(sEa, 72, 0, sWhi0, sWlo0, wm, wn, g, tg, acc1);
        sts_w(wreg, sWhi1, tid);
#pragma unroll
        for (int mt = 0; mt < 2; mt++) {
            int r0 = wm * 32 + mt * 16 + g;
            int r1 = r0 + 8;
#pragma unroll
            for (int nt = 0; nt < 8; nt++) {
                int cc = wn * 64 + nt * 8 + tg * 2;
                float2 bv = *(const float2*)(b1 + cc);
                float vx0 = sspf(acc1[mt][nt][0] + bv.x);
                float vy0 = sspf(acc1[mt][nt][1] + bv.y);
                float vx1 = sspf(acc1[mt][nt][2] + bv.x);
                float vy1 = sspf(acc1[mt][nt][3] + bv.y);
                *(__nv_bfloat162*)(sT + r0 * 136 + cc) = __floats2bfloat162_rn(vx0, vy0);
                *(__nv_bfloat162*)(sT + r1 * 136 + cc) = __floats2bfloat162_rn(vx1, vy1);
            }
        }
    }
    __syncthreads();

    // ---- GEMM2: T = (H @ Wf2 + bf2) * cutoff(row) -> g_Tb ----
    {
        float acc2[2][8][4] = {};
        ldg_w(cWf2 + SLOT_ELEMS, wreg, tid);
        mma_half<8>(sT, 136, 0, sWhi1, sWlo1, wm, wn, g, tg, acc2);
        sts_w(wreg, sWhi0, tid);
        __syncthreads();
        mma_half<8>(sT, 136, 1, sWhi0, sWlo0, wm, wn, g, tg, acc2);
        __nv_bfloat16* outB = g_Tb + (size_t)inter * NTAB * HID;
#pragma unroll
        for (int mt = 0; mt < 2; mt++) {
            int r0 = row0 + wm * 32 + mt * 16 + g;
            int r1 = r0 + 8;
            float s0 = 0.5f * (cosf((float)r0 * DELTA * PI_O10) + 1.0f);
            float s1 = 0.5f * (cosf((float)r1 * DELTA * PI_O10) + 1.0f);
#pragma unroll
            for (int nt = 0; nt < 8; nt++) {
                int cc = wn * 64 + nt * 8 + tg * 2;
                float2 bv = *(const float2*)(b2 + cc);
                float vx0 = (acc2[mt][nt][0] + bv.x) * s0;
                float vy0 = (acc2[mt][nt][1] + bv.y) * s0;
                float vx1 = (acc2[mt][nt][2] + bv.x) * s1;
                float vy1 = (acc2[mt][nt][3] + bv.y) * s1;
                *(__nv_bfloat162*)(outB + (size_t)r0 * 128 + cc) = __floats2bfloat162_rn(vx0, vy0);
                *(__nv_bfloat162*)(outB + (size_t)r1 * 128 + cc) = __floats2bfloat162_rn(vx1, vy1);
            }
        }
    }
}

// ---------------- standalone GEMM: x0 = hb @ Wl1[0] ----------------
__global__ __launch_bounds__(256) void gemm_x0(
    const __nv_bfloat16* __restrict__ A, __nv_bfloat16* __restrict__ outB)
{
    __shared__ __nv_bfloat16 sBhi[2 * 128 * 72];   // hi + lo contiguous

    const int tid = threadIdx.x;
    const int w = tid >> 5, lane = tid & 31;
    const int wm = w >> 1, wn = w & 1;
    const int g = lane >> 2, tg = lane & 3;
    const int row0 = blockIdx.x * 128;

    const __nv_bfloat16* cW = g_Wc + (size_t)24 * SLOT_ELEMS;   // Wl1[0] kh0/kh1
    __nv_bfloat16* sBlo = sBhi + 128 * 72;

    float acc[2][8][4] = {};
    const __nv_bfloat16* aBase = A + (size_t)row0 * 128;
    uint4 wreg[9];

    ldg_w(cW, wreg, tid);
    sts_w(wreg, sBhi, tid);
    __syncthreads();
    ldg_w(cW + SLOT_ELEMS, wreg, tid);
    mma_half<8>(aBase, 128, 0, sBhi, sBlo, wm, wn, g, tg, acc);
    __syncthreads();
    sts_w(wreg, sBhi, tid);
    __syncthreads();
    mma_half<8>(aBase, 128, 1, sBhi, sBlo, wm, wn, g, tg, acc);

#pragma unroll
    for (int mt = 0; mt < 2; mt++) {
        int r0 = row0 + wm * 32 + mt * 16 + g;
        int r1 = r0 + 8;
#pragma unroll
        for (int nt = 0; nt < 8; nt++) {
            int cc = wn * 64 + nt * 8 + tg * 2;
            *(__nv_bfloat162*)(outB + (size_t)r0 * 128 + cc) =
                __floats2bfloat162_rn(acc[mt][nt][0], acc[mt][nt][1]);
            *(__nv_bfloat162*)(outB + (size_t)r1 * 128 + cc) =
                __floats2bfloat162_rn(acc[mt][nt][2], acc[mt][nt][3]);
        }
    }
}

// ---------------- fused interaction update: 3 chained GEMMs, copy-staged weights ----------------
template <bool LAST>
__global__ __launch_bounds__(256) void fused_update(
    const __nv_bfloat16* __restrict__ aggb,
    float* __restrict__ h,
    const __nv_bfloat16* __restrict__ cWl2, const float* __restrict__ bl2,
    const __nv_bfloat16* __restrict__ cWl,  const float* __restrict__ bl,
    const __nv_bfloat16* __restrict__ cW3,
    const float* __restrict__ bo1, const float* __restrict__ Wo2,
    __nv_bfloat16* __restrict__ xb)
{
    extern __shared__ __align__(16) char smem_raw[];
    __nv_bfloat16* sWhi0 = (__nv_bfloat16*)smem_raw;     // 128*72
    __nv_bfloat16* sWlo0 = sWhi0 + 128 * 72;
    __nv_bfloat16* sWhi1 = sWlo0 + 128 * 72;
    __nv_bfloat16* sWlo1 = sWhi1 + 128 * 72;
    __nv_bfloat16* sT    = sWlo1 + 128 * 72;             // 128*136
    __nv_bfloat16* sHn   = sT + 128 * 136;               // 128*136

    const int tid = threadIdx.x;
    const int w = tid >> 5, lane = tid & 31;
    const int wm = w >> 1, wn = w & 1;
    const int g = lane >> 2, tg = lane & 3;
    const int row0 = blockIdx.x * 128;

    uint4 wreg[9];
    const __nv_bfloat16* aggA = aggb + (size_t)row0 * 128;

    // preload (Wl2, kh0)
    ldg_w(cWl2, wreg, tid);
    sts_w(wreg, sWhi0, tid);
    __syncthreads();

    // ======== stage 1: t = ssp(aggb @ Wl2 + bl2) ========
    float acc1[2][8][4] = {};
    ldg_w(cWl2 + SLOT_ELEMS, wreg, tid);
    mma_half<8>(aggA, 128, 0, sWhi0, sWlo0, wm, wn, g, tg, acc1);
    sts_w(wreg, sWhi1, tid);
    __syncthreads();

    ldg_w(cWl, wreg, tid);
    mma_half<8>(aggA, 128, 1, sWhi1, sWlo1, wm, wn, g, tg, acc1);
    sts_w(wreg, sWhi0, tid);
    {
#pragma unroll
        for (int mt = 0; mt < 2; mt++) {
            int r0 = wm * 32 + mt * 16 + g;
            int r1 = r0 + 8;
#pragma unroll
            for (int nt = 0; nt < 8; nt++) {
                int cc = wn * 64 + nt * 8 + tg * 2;
                float2 bv = *(const float2*)(bl2 + cc);
                float vx0 = sspf(acc1[mt][nt][0] + bv.x);
                float vy0 = sspf(acc1[mt][nt][1] + bv.y);
                float vx1 = sspf(acc1[mt][nt][2] + bv.x);
                float vy1 = sspf(acc1[mt][nt][3] + bv.y);
                *(__nv_bfloat162*)(sT + r0 * 136 + cc) = __floats2bfloat162_rn(vx0, vy0);
                *(__nv_bfloat162*)(sT + r1 * 136 + cc) = __floats2bfloat162_rn(vx1, vy1);
            }
        }
    }
    __syncthreads();

    // ======== stage 2: hn = t @ Wl + bl + h ========
    float acc2[2][8][4] = {};
    ldg_w(cWl + SLOT_ELEMS, wreg, tid);
    mma_half<8>(sT, 136, 0, sWhi0, sWlo0, wm, wn, g, tg, acc2);
    sts_w(wreg, sWhi1, tid);
    __syncthreads();

    ldg_w(cW3, wreg, tid);
    mma_half<8>(sT, 136, 1, sWhi1, sWlo1, wm, wn, g, tg, acc2);
    sts_w(wreg, sWhi0, tid);
    {
#pragma unroll
        for (int mt = 0; mt < 2; mt++) {
            int r0 = wm * 32 + mt * 16 + g;
            int r1 = r0 + 8;
            float* h0p = h + (size_t)(row0 + r0) * 128;
            float* h1p = h + (size_t)(row0 + r1) * 128;
#pragma unroll
            for (int nt = 0; nt < 8; nt++) {
                int cc = wn * 64 + nt * 8 + tg * 2;
                float2 bv = *(const float2*)(bl + cc);
                float2 e0 = *(const float2*)(h0p + cc);
                float2 e1 = *(const float2*)(h1p + cc);
                float vx0 = acc2[mt][nt][0] + bv.x + e0.x;
                float vy0 = acc2[mt][nt][1] + bv.y + e0.y;
                float vx1 = acc2[mt][nt][2] + bv.x + e1.x;
                float vy1 = acc2[mt][nt][3] + bv.y + e1.y;
                *(float2*)(h0p + cc) = make_float2(vx0, vy0);
                *(float2*)(h1p + cc) = make_float2(vx1, vy1);
                *(__nv_bfloat162*)(sHn + r0 * 136 + cc) = __floats2bfloat162_rn(vx0, vy0);
                *(__nv_bfloat162*)(sHn + r1 * 136 + cc) = __floats2bfloat162_rn(vx1, vy1);
            }
        }
    }
    __syncthreads();

    // ======== stage 3: next x or readout ========
    if (!LAST) {
        float acc3[2][8][4] = {};
        ldg_w(cW3 + SLOT_ELEMS, wreg, tid);
        mma_half<8>(sHn, 136, 0, sWhi0, sWlo0, wm, wn, g, tg, acc3);
        sts_w(wreg, sWhi1, tid);
        __syncthreads();
        mma_half<8>(sHn, 136, 1, sWhi1, sWlo1, wm, wn, g, tg, acc3);
#pragma unroll
        for (int mt = 0; mt < 2; mt++) {
            int r0 = row0 + wm * 32 + mt * 16 + g;
            int r1 = r0 + 8;
#pragma unroll
            for (int nt = 0; nt < 8; nt++) {
                int cc = wn * 64 + nt * 8 + tg * 2;
                *(__nv_bfloat162*)(xb + (size_t)r0 * 128 + cc) =
                    __floats2bfloat162_rn(acc3[mt][nt][0], acc3[mt][nt][1]);
                *(__nv_bfloat162*)(xb + (size_t)r1 * 128 + cc) =
                    __floats2bfloat162_rn(acc3[mt][nt][2], acc3[mt][nt][3]);
            }
        }
    } else {
        float acc3[2][4][4] = {};
        ldg_w(cW3 + SLOT_ELEMS, wreg, tid);
        mma_half<4>(sHn, 136, 0, sWhi0, sWlo0, wm, wn, g, tg, acc3);
        sts_w(wreg, sWhi1, tid);
        __syncthreads();
        mma_half<4>(sHn, 136, 1, sWhi1, sWlo1, wm, wn, g, tg, acc3);
        float v = 0.0f;
#pragma unroll
        for (int mt = 0; mt < 2; mt++) {
#pragma unroll
            for (int nt = 0; nt < 4; nt++) {
                int cc = wn * 32 + nt * 8 + tg * 2;
                float2 bo = *(const float2*)(bo1 + cc);
                float2 w2 = *(const float2*)(Wo2 + cc);
                v += sspf(acc3[mt][nt][0] + bo.x) * w2.x + sspf(acc3[mt][nt][1] + bo.y) * w2.y;
                v += sspf(acc3[mt][nt][2] + bo.x) * w2.x + sspf(acc3[mt][nt][3] + bo.y) * w2.y;
            }
        }
#pragma unroll
        for (int off = 16; off > 0; off >>= 1)
            v += __shfl_xor_sync(0xFFFFFFFFu, v, off);
        if (lane == 0) atomicAdd(&g_sum, v);
    }
}

// ---------------- edge aggregation (dst-sorted, warp/node, nearest table) ----------------
__device__ __forceinline__ void edge_acc(const __nv_bfloat16* xb, const __nv_bfloat16* Tb,
                                         int pk, int lane, float4& acc) {
    int s = pk & 16383;
    int t0 = pk >> 14;
    uint2 xv = ((const uint2*)(xb + (size_t)s * 128))[lane];
    uint2 tv = ((const uint2*)(Tb + (size_t)t0 * 128))[lane];
    float2 x0 = __bfloat1622float2(*(__nv_bfloat162*)&xv.x);
    float2 x1 = __bfloat1622float2(*(__nv_bfloat162*)&xv.y);
    float2 f0 = __bfloat1622float2(*(__nv_bfloat162*)&tv.x);
    float2 f1 = __bfloat1622float2(*(__nv_bfloat162*)&tv.y);
    acc.x += x0.x * f0.x;
    acc.y += x0.y * f0.y;
    acc.z += x1.x * f1.x;
    acc.w += x1.y * f1.y;
}

__global__ void agg_kernel(const __nv_bfloat16* __restrict__ xb,
                           const __nv_bfloat16* __restrict__ Tb) {
    int warp = (blockIdx.x * blockDim.x + threadIdx.x) >> 5;
    int lane = threadIdx.x & 31;
    if (warp >= NN) return;
    int b = g_start[warp];
    int e = g_start[warp + 1];
    float4 acc = make_float4(0.f, 0.f, 0.f, 0.f);
    int j = b;
    for (; j + 4 <= e; j += 4) {
        int pk0 = g_perm[j],     pk1 = g_perm[j + 1];
        int pk2 = g_perm[j + 2], pk3 = g_perm[j + 3];
        edge_acc(xb, Tb, pk0, lane, acc);
        edge_acc(xb, Tb, pk1, lane, acc);
        edge_acc(xb, Tb, pk2, lane, acc);
        edge_acc(xb, Tb, pk3, lane, acc);
    }
    for (; j < e; j++) edge_acc(xb, Tb, g_perm[j], lane, acc);
    __nv_bfloat162 o0 = __floats2bfloat162_rn(acc.x, acc.y);
    __nv_bfloat162 o1 = __floats2bfloat162_rn(acc.z, acc.w);
    uint2 ov;
    ov.x = *(uint32_t*)&o0;
    ov.y = *(uint32_t*)&o1;
    ((uint2*)(g_aggb + (size_t)warp * 128))[lane] = ov;
}

__global__ void final_kernel(float* __restrict__ out, const float* __restrict__ bo2) {
    float v = g_sum + (float)NN * bo2[0];
    out[0] = fmaxf(v, 0.0f);
}

// ---------------- launch ----------------
extern "C" void kernel_launch(void* const* d_in, const int* in_sizes, int n_in,
                              void* d_out, int out_size) {
    const int*   z    = (const int*)d_in[0];
    const float* pos  = (const float*)d_in[1];
    const int*   ei   = (const int*)d_in[2];
    const float* emb  = (const float*)d_in[3];
    const float* Wf1  = (const float*)d_in[4];
    const float* bf1  = (const float*)d_in[5];
    const float* Wf2  = (const float*)d_in[6];
    const float* bf2  = (const float*)d_in[7];
    const float* Wl1  = (const float*)d_in[8];
    const float* Wl2  = (const float*)d_in[9];
    const float* bl2  = (const float*)d_in[10];
    const float* Wl   = (const float*)d_in[11];
    const float* bl   = (const float*)d_in[12];
    const float* Wo1  = (const float*)d_in[13];
    const float* bo1  = (const float*)d_in[14];
    const float* Wo2  = (const float*)d_in[15];
    const float* bo2  = (const float*)d_in[16];
    float* out = (float*)d_out;

    float *p_h;
    __nv_bfloat16 *p_hb, *p_xb, *p_aggb, *p_Tb, *p_Wc;
    cudaGetSymbolAddress((void**)&p_h,    g_h);
    cudaGetSymbolAddress((void**)&p_hb,   g_hb);
    cudaGetSymbolAddress((void**)&p_xb,   g_xb);
    cudaGetSymbolAddress((void**)&p_aggb, g_aggb);
    cudaGetSymbolAddress((void**)&p_Tb,   g_Tb);
    cudaGetSymbolAddress((void**)&p_Wc,   g_Wc);

    const int FUSED_SMEM = (4 * 128 * 72 + 2 * 128 * 136) * (int)sizeof(__nv_bfloat16);
    const int TABLE_SMEM = (5 * 128 * 72 + 128 * 136) * (int)sizeof(__nv_bfloat16);
    cudaFuncSetAttribute(fused_update<false>, cudaFuncAttributeMaxDynamicSharedMemorySize, FUSED_SMEM);
    cudaFuncSetAttribute(fused_update<true>,  cudaFuncAttributeMaxDynamicSharedMemorySize, FUSED_SMEM);
    cudaFuncSetAttribute(tableT_kernel, cudaFuncAttributeMaxDynamicSharedMemorySize, TABLE_SMEM);

    // --- weight preconversion (independent; head of graph) ---
    convW_kernel<<<NSLOT, 256>>>(Wl2, Wl, Wl1, Wo1, Wf1, Wf2);

    // --- edge prep + dst sort ---
    zero_kernel<<<NN / 256, 256>>>();
    prep_kernel<<<EE / 256, 256>>>(pos, ei);
    scan_kernel<<<1, 1024>>>();
    scatter_kernel<<<EE / 256, 256>>>(ei);
    emb_kernel<<<NN * HID / 256, 256>>>(z, emb);

    // --- filter tables, all-MMA (batched over 6 interactions) ---
    tableT_kernel<<<dim3(NTAB / 128, NINTER), 256, TABLE_SMEM>>>(bf1, bf2);

    // --- first x = h @ Wl1[0] ---
    gemm_x0<<<NN / 128, 256>>>(p_hb, p_xb);

    // --- interaction blocks: agg + fused pipelined update ---
    for (int i = 0; i < NINTER; i++) {
        agg_kernel<<<NN / 8, 256>>>(p_xb, p_Tb + (size_t)i * NTAB * HID);
        const __nv_bfloat16* cWl2 = p_Wc + (size_t)(2 * i) * SLOT_ELEMS;
        const __nv_bfloat16* cWl  = p_Wc + (size_t)(12 + 2 * i) * SLOT_ELEMS;
        if (i < NINTER - 1) {
            const __nv_bfloat16* cW3 = p_Wc + (size_t)(24 + 2 * (i + 1)) * SLOT_ELEMS;
            fused_update<false><<<NN / 128, 256, FUSED_SMEM>>>(
                p_aggb, p_h,
                cWl2, bl2 + (size_t)i * HID,
                cWl,  bl  + (size_t)i * HID,
                cW3, nullptr, nullptr, p_xb);
        } else {
            const __nv_bfloat16* cW3 = p_Wc + (size_t)36 * SLOT_ELEMS;
            fused_update<true><<<NN / 128, 256, FUSED_SMEM>>>(
                p_aggb, p_h,
                cWl2, bl2 + (size_t)i * HID,
                cWl,  bl  + (size_t)i * HID,
                cW3, bo1, Wo2, nullptr);
        }
    }

    final_kernel<<<1, 1>>>(out, bo2);
}

// round 15
// speedup vs baseline: 1.4749x; 1.0155x over previous
#include <cuda_runtime.h>
#include <cuda_bf16.h>
#include <math.h>
#include <cstdint>

#define NN      16384
#define EE      262144
#define HID     128
#define NGAUSS  50
#define NINTER  6
#define NTAB    8192
#define DMAX    8.6610f
#define DELTA   (DMAX / (float)(NTAB - 1))
#define GSPACE  (10.0f / 49.0f)
#define GCOEFF  (-0.5f / (GSPACE * GSPACE))
#define LOG2F_C 0.69314718055994530942f
#define PI_O10  0.31415926535897932f

#define SLOT_ELEMS 18432   // one 64x128 chunk: hi[128*72] + lo[128*72] bf16
#define NSLOT 56

// ---------------- device scratch ----------------
__device__ float g_d[EE];
__device__ int   g_perm[EE];               // packed (t0 << 14) | src
__device__ int   g_start[NN + 1];
__device__ int   g_cnt[NN];
__device__ float g_h[NN * HID];            // fp32 residual stream
__device__ __nv_bfloat16 g_hb[NN * HID];   // bf16 shadow (first x GEMM)
__device__ __nv_bfloat16 g_xb[NN * HID];
__device__ __nv_bfloat16 g_aggb[NN * HID];
__device__ __nv_bfloat16 g_Tb[NINTER * NTAB * HID];
__device__ __nv_bfloat16 g_Wc[NSLOT * SLOT_ELEMS];   // preconverted weights
__device__ float g_sum;

__device__ __forceinline__ float sspf(float x) {
    float sp = (x > 15.0f) ? x : log1pf(expf(x));
    return sp - LOG2F_C;
}

// ---------------- prep kernels ----------------
__global__ void zero_kernel() {
    int i = blockIdx.x * blockDim.x + threadIdx.x;
    if (i < NN) g_cnt[i] = 0;
    if (i == 0) g_sum = 0.0f;
}

__global__ void prep_kernel(const float* __restrict__ pos, const int* __restrict__ ei) {
    int e = blockIdx.x * blockDim.x + threadIdx.x;
    if (e >= EE) return;
    int s = ei[e];
    int t = ei[EE + e];
    float dx = pos[3 * s + 0] - pos[3 * t + 0];
    float dy = pos[3 * s + 1] - pos[3 * t + 1];
    float dz = pos[3 * s + 2] - pos[3 * t + 2];
    g_d[e] = sqrtf(dx * dx + dy * dy + dz * dz);
    atomicAdd(&g_cnt[t], 1);
}

// shuffle-based scan: 1024 threads x 16 elements, 2 barriers total
__global__ void scan_kernel() {
    __shared__ int warpsum[32];
    const int tid = threadIdx.x;
    const int lane = tid & 31, wid = tid >> 5;
    const int base = tid * 16;

    int loc[16];
    const int4* cnt4 = (const int4*)(g_cnt + base);
#pragma unroll
    for (int q = 0; q < 4; q++) {
        int4 v = cnt4[q];
        loc[4 * q + 0] = v.x; loc[4 * q + 1] = v.y;
        loc[4 * q + 2] = v.z; loc[4 * q + 3] = v.w;
    }
    int s = 0;
#pragma unroll
    for (int i = 0; i < 16; i++) s += loc[i];

    // inclusive warp scan of s
    int ps = s;
#pragma unroll
    for (int off = 1; off < 32; off <<= 1) {
        int v = __shfl_up_sync(0xFFFFFFFFu, ps, off);
        if (lane >= off) ps += v;
    }
    if (lane == 31) warpsum[wid] = ps;
    __syncthreads();
    if (wid == 0) {
        int ws = warpsum[lane];
#pragma unroll
        for (int off = 1; off < 32; off <<= 1) {
            int v = __shfl_up_sync(0xFFFFFFFFu, ws, off);
            if (lane >= off) ws += v;
        }
        warpsum[lane] = ws;
    }
    __syncthreads();

    int excl = ps - s + ((wid > 0) ? warpsum[wid - 1] : 0);
#pragma unroll
    for (int i = 0; i < 16; i++) {
        g_start[base + i] = excl;
        g_cnt[base + i] = excl;   // cursor init
        excl += loc[i];
    }
    if (tid == 1023) g_start[NN] = excl;
}

__global__ void scatter_kernel(const int* __restrict__ ei) {
    int e = blockIdx.x * blockDim.x + threadIdx.x;
    if (e >= EE) return;
    int t = ei[EE + e];
    int s = ei[e];
    float f = g_d[e] * (1.0f / DELTA);
    int t0 = (int)(f + 0.5f);              // nearest table entry
    t0 = min(t0, NTAB - 1);
    int p = atomicAdd(&g_cnt[t], 1);
    g_perm[p] = (t0 << 14) | s;
}

__global__ void emb_kernel(const int* __restrict__ z, const float* __restrict__ emb) {
    int idx = blockIdx.x * blockDim.x + threadIdx.x;
    if (idx >= NN * HID) return;
    int n = idx >> 7, c = idx & 127;
    float v = emb[z[n] * HID + c];
    g_h[idx] = v;
    g_hb[idx] = __float2bfloat16(v);
}

// ---------------- weight preconversion: fp32 -> hi/lo bf16 in fragment layout ----------------
// slot map: 0..11 Wl2[i](kh), 12..23 Wl[i](kh), 24..35 Wl1[i](kh),
//           36..37 Wo1(kh, NC=64), 38..43 Wf1[i](padded K), 44..55 Wf2[i](kh)
__global__ void convW_kernel(const float* __restrict__ Wl2, const float* __restrict__ Wl,
                             const float* __restrict__ Wl1, const float* __restrict__ Wo1,
                             const float* __restrict__ Wf1, const float* __restrict__ Wf2) {
    int slot = blockIdx.x;
    int tid = threadIdx.x;
    __nv_bfloat16* dst = g_Wc + (size_t)slot * SLOT_ELEMS;
    const float* src;
    int kh, NC = 128;
    bool padK = false;
    if (slot < 12)      { src = Wl2 + (size_t)(slot >> 1) * 16384; kh = slot & 1; }
    else if (slot < 24) { src = Wl  + (size_t)((slot - 12) >> 1) * 16384; kh = slot & 1; }
    else if (slot < 36) { src = Wl1 + (size_t)((slot - 24) >> 1) * 16384; kh = slot & 1; }
    else if (slot < 38) { src = Wo1; kh = slot - 36; NC = 64; }
    else if (slot < 44) { src = Wf1 + (size_t)(slot - 38) * NGAUSS * 128; kh = 0; padK = true; }
    else                { src = Wf2 + (size_t)((slot - 44) >> 1) * 16384; kh = slot & 1; }

    for (int flat = tid; flat < 128 * 64; flat += 256) {
        int n = flat >> 6, kp = flat & 63;
        int krow = kh * 64 + kp;
        float v = 0.0f;
        if (n < NC && !(padK && krow >= NGAUSS))
            v = src[(size_t)krow * NC + n];
        __nv_bfloat16 h = __float2bfloat16(v);
        dst[n * 72 + kp] = h;
        dst[9216 + n * 72 + kp] = __float2bfloat16(v - __bfloat162float(h));
    }
}

// ---------------- MMA helpers ----------------
#define MMA16816(d, a, b0, b1) \
    asm volatile("mma.sync.aligned.m16n8k16.row.col.f32.bf16.bf16.f32 " \
        "{%0,%1,%2,%3}, {%4,%5,%6,%7}, {%8,%9}, {%0,%1,%2,%3};" \
        : "+f"((d)[0]), "+f"((d)[1]), "+f"((d)[2]), "+f"((d)[3]) \
        : "r"((a)[0]), "r"((a)[1]), "r"((a)[2]), "r"((a)[3]), "r"(b0), "r"(b1))

// ---------------- preconverted-weight staging (pure copy) ----------------
__device__ __forceinline__ void ldg_w(const __nv_bfloat16* __restrict__ src,
                                      uint4* wreg, int tid) {
    const uint4* s = (const uint4*)src;
#pragma unroll
    for (int i = 0; i < 9; i++) wreg[i] = s[tid + i * 256];
}
__device__ __forceinline__ void sts_w(const uint4* wreg, __nv_bfloat16* dsthi, int tid) {
    uint4* d = (uint4*)dsthi;
#pragma unroll
    for (int i = 0; i < 9; i++) d[tid + i * 256] = wreg[i];
}

template <int NT>
__device__ __forceinline__ void mma_half(
    const __nv_bfloat16* __restrict__ A, int lda, int kh,
    const __nv_bfloat16* hi, const __nv_bfloat16* lo,
    int wm, int wn, int g, int tg, float acc[2][NT][4])
{
    const __nv_bfloat16* rp0 = A + (wm * 32 + g) * lda;
    const int colbase = wn * (NT * 8);
#pragma unroll
    for (int ks = 0; ks < 4; ks++) {
        int kc = kh * 64 + ks * 16 + tg * 2;
        uint32_t af[2][4];
#pragma unroll
        for (int mt = 0; mt < 2; mt++) {
            const __nv_bfloat16* rp = rp0 + mt * 16 * lda;
            af[mt][0] = *(const uint32_t*)(rp + kc);
            af[mt][1] = *(const uint32_t*)(rp + 8 * lda + kc);
            af[mt][2] = *(const uint32_t*)(rp + kc + 8);
            af[mt][3] = *(const uint32_t*)(rp + 8 * lda + kc + 8);
        }
        int c = ks * 16 + tg * 2;
#pragma unroll
        for (int nt = 0; nt < NT; nt++) {
            int n = colbase + nt * 8 + g;
            uint32_t bh0 = *(const uint32_t*)(hi + n * 72 + c);
            uint32_t bh1 = *(const uint32_t*)(hi + n * 72 + c + 8);
            uint32_t bl0 = *(const uint32_t*)(lo + n * 72 + c);
            uint32_t bl1 = *(const uint32_t*)(lo + n * 72 + c + 8);
#pragma unroll
            for (int mt = 0; mt < 2; mt++) {
                MMA16816(acc[mt][nt], af[mt], bh0, bh1);
                MMA16816(acc[mt][nt], af[mt], bl0, bl1);
            }
        }
    }
}

// ---------------- filter-table builder: ea->GEMM->ssp->GEMM->cutoff ----------------
__global__ __launch_bounds__(256) void tableT_kernel(
    const float* __restrict__ bf1, const float* __restrict__ bf2)
{
    extern __shared__ __align__(16) char smem_raw[];
    __nv_bfloat16* sWhi0 = (__nv_bfloat16*)smem_raw;     // 128*72
    __nv_bfloat16* sWlo0 = sWhi0 + 128 * 72;
    __nv_bfloat16* sWhi1 = sWlo0 + 128 * 72;
    __nv_bfloat16* sWlo1 = sWhi1 + 128 * 72;
    __nv_bfloat16* sEa   = sWlo1 + 128 * 72;             // 128*72 (K=64 padded)
    __nv_bfloat16* sT    = sEa + 128 * 72;               // 128*136

    const int tid = threadIdx.x;
    const int w = tid >> 5, lane = tid & 31;
    const int wm = w >> 1, wn = w & 1;
    const int g = lane >> 2, tg = lane & 3;
    const int inter = blockIdx.y;
    const int row0 = blockIdx.x * 128;

    const __nv_bfloat16* cWf1 = g_Wc + (size_t)(38 + inter) * SLOT_ELEMS;
    const __nv_bfloat16* cWf2 = g_Wc + (size_t)(44 + 2 * inter) * SLOT_ELEMS;
    const float* b1 = bf1 + (size_t)inter * HID;
    const float* b2 = bf2 + (size_t)inter * HID;

    // Gaussian rows (bf16, K padded to 64)
    for (int idx = tid; idx < 128 * 64; idx += 256) {
        int r = idx >> 6, k = idx & 63;
        float v = 0.0f;
        if (k < NGAUSS) {
            float u = (float)(row0 + r) * DELTA - (float)k * GSPACE;
            v = expf(GCOEFF * u * u);
        }
        sEa[r * 72 + k] = __float2bfloat16(v);
    }

    uint4 wreg[9];
    ldg_w(cWf1, wreg, tid);
    sts_w(wreg, sWhi0, tid);
    __syncthreads();

    // ---- GEMM1: H = ssp(ea @ Wf1 + bf1) -> sT ----
    {
        float acc1[2][8][4] = {};
        ldg_w(cWf2, wreg, tid);
        mma_half<8>(sEa, 72, 0, sWhi0, sWlo0, wm, wn, g, tg, acc1);
        sts_w(wreg, sWhi1, tid);
#pragma unroll
        for (int mt = 0; mt < 2; mt++) {
            int r0 = wm * 32 + mt * 16 + g;
            int r1 = r0 + 8;
#pragma unroll
            for (int nt = 0; nt < 8; nt++) {
                int cc = wn * 64 + nt * 8 + tg * 2;
                float2 bv = *(const float2*)(b1 + cc);
                float vx0 = sspf(acc1[mt][nt][0] + bv.x);
                float vy0 = sspf(acc1[mt][nt][1] + bv.y);
                float vx1 = sspf(acc1[mt][nt][2] + bv.x);
                float vy1 = sspf(acc1[mt][nt][3] + bv.y);
                *(__nv_bfloat162*)(sT + r0 * 136 + cc) = __floats2bfloat162_rn(vx0, vy0);
                *(__nv_bfloat162*)(sT + r1 * 136 + cc) = __floats2bfloat162_rn(vx1, vy1);
            }
        }
    }
    __syncthreads();

    // ---- GEMM2: T = (H @ Wf2 + bf2) * cutoff(row) -> g_Tb ----
    {
        float acc2[2][8][4] = {};
        ldg_w(cWf2 + SLOT_ELEMS, wreg, tid);
        mma_half<8>(sT, 136, 0, sWhi1, sWlo1, wm, wn, g, tg, acc2);
        sts_w(wreg, sWhi0, tid);
        __syncthreads();
        mma_half<8>(sT, 136, 1, sWhi0, sWlo0, wm, wn, g, tg, acc2);
        __nv_bfloat16* outB = g_Tb + (size_t)inter * NTAB * HID;
#pragma unroll
        for (int mt = 0; mt < 2; mt++) {
            int r0 = row0 + wm * 32 + mt * 16 + g;
            int r1 = r0 + 8;
            float s0 = 0.5f * (cosf((float)r0 * DELTA * PI_O10) + 1.0f);
            float s1 = 0.5f * (cosf((float)r1 * DELTA * PI_O10) + 1.0f);
#pragma unroll
            for (int nt = 0; nt < 8; nt++) {
                int cc = wn * 64 + nt * 8 + tg * 2;
                float2 bv = *(const float2*)(b2 + cc);
                float vx0 = (acc2[mt][nt][0] + bv.x) * s0;
                float vy0 = (acc2[mt][nt][1] + bv.y) * s0;
                float vx1 = (acc2[mt][nt][2] + bv.x) * s1;
                float vy1 = (acc2[mt][nt][3] + bv.y) * s1;
                *(__nv_bfloat162*)(outB + (size_t)r0 * 128 + cc) = __floats2bfloat162_rn(vx0, vy0);
                *(__nv_bfloat162*)(outB + (size_t)r1 * 128 + cc) = __floats2bfloat162_rn(vx1, vy1);
            }
        }
    }
}

// ---------------- standalone GEMM: x0 = hb @ Wl1[0] ----------------
__global__ __launch_bounds__(256) void gemm_x0(
    const __nv_bfloat16* __restrict__ A, __nv_bfloat16* __restrict__ outB)
{
    __shared__ __nv_bfloat16 sBhi[2 * 128 * 72];   // hi + lo contiguous

    const int tid = threadIdx.x;
    const int w = tid >> 5, lane = tid & 31;
    const int wm = w >> 1, wn = w & 1;
    const int g = lane >> 2, tg = lane & 3;
    const int row0 = blockIdx.x * 128;

    const __nv_bfloat16* cW = g_Wc + (size_t)24 * SLOT_ELEMS;   // Wl1[0] kh0/kh1
    __nv_bfloat16* sBlo = sBhi + 128 * 72;

    float acc[2][8][4] = {};
    const __nv_bfloat16* aBase = A + (size_t)row0 * 128;
    uint4 wreg[9];

    ldg_w(cW, wreg, tid);
    sts_w(wreg, sBhi, tid);
    __syncthreads();
    ldg_w(cW + SLOT_ELEMS, wreg, tid);
    mma_half<8>(aBase, 128, 0, sBhi, sBlo, wm, wn, g, tg, acc);
    __syncthreads();
    sts_w(wreg, sBhi, tid);
    __syncthreads();
    mma_half<8>(aBase, 128, 1, sBhi, sBlo, wm, wn, g, tg, acc);

#pragma unroll
    for (int mt = 0; mt < 2; mt++) {
        int r0 = row0 + wm * 32 + mt * 16 + g;
        int r1 = r0 + 8;
#pragma unroll
        for (int nt = 0; nt < 8; nt++) {
            int cc = wn * 64 + nt * 8 + tg * 2;
            *(__nv_bfloat162*)(outB + (size_t)r0 * 128 + cc) =
                __floats2bfloat162_rn(acc[mt][nt][0], acc[mt][nt][1]);
            *(__nv_bfloat162*)(outB + (size_t)r1 * 128 + cc) =
                __floats2bfloat162_rn(acc[mt][nt][2], acc[mt][nt][3]);
        }
    }
}

// ---------------- fused interaction update: 3 chained GEMMs, copy-staged weights ----------------
template <bool LAST>
__global__ __launch_bounds__(256) void fused_update(
    const __nv_bfloat16* __restrict__ aggb,
    float* __restrict__ h,
    const __nv_bfloat16* __restrict__ cWl2, const float* __restrict__ bl2,
    const __nv_bfloat16* __restrict__ cWl,  const float* __restrict__ bl,
    const __nv_bfloat16* __restrict__ cW3,
    const float* __restrict__ bo1, const float* __restrict__ Wo2,
    __nv_bfloat16* __restrict__ xb)
{
    extern __shared__ __align__(16) char smem_raw[];
    __nv_bfloat16* sWhi0 = (__nv_bfloat16*)smem_raw;     // 128*72
    __nv_bfloat16* sWlo0 = sWhi0 + 128 * 72;
    __nv_bfloat16* sWhi1 = sWlo0 + 128 * 72;
    __nv_bfloat16* sWlo1 = sWhi1 + 128 * 72;
    __nv_bfloat16* sT    = sWlo1 + 128 * 72;             // 128*136
    __nv_bfloat16* sHn   = sT + 128 * 136;               // 128*136

    const int tid = threadIdx.x;
    const int w = tid >> 5, lane = tid & 31;
    const int wm = w >> 1, wn = w & 1;
    const int g = lane >> 2, tg = lane & 3;
    const int row0 = blockIdx.x * 128;

    uint4 wreg[9];
    const __nv_bfloat16* aggA = aggb + (size_t)row0 * 128;

    // preload (Wl2, kh0)
    ldg_w(cWl2, wreg, tid);
    sts_w(wreg, sWhi0, tid);
    __syncthreads();

    // ======== stage 1: t = ssp(aggb @ Wl2 + bl2) ========
    float acc1[2][8][4] = {};
    ldg_w(cWl2 + SLOT_ELEMS, wreg, tid);
    mma_half<8>(aggA, 128, 0, sWhi0, sWlo0, wm, wn, g, tg, acc1);
    sts_w(wreg, sWhi1, tid);
    __syncthreads();

    ldg_w(cWl, wreg, tid);
    mma_half<8>(aggA, 128, 1, sWhi1, sWlo1, wm, wn, g, tg, acc1);
    sts_w(wreg, sWhi0, tid);
    {
#pragma unroll
        for (int mt = 0; mt < 2; mt++) {
            int r0 = wm * 32 + mt * 16 + g;
            int r1 = r0 + 8;
#pragma unroll
            for (int nt = 0; nt < 8; nt++) {
                int cc = wn * 64 + nt * 8 + tg * 2;
                float2 bv = *(const float2*)(bl2 + cc);
                float vx0 = sspf(acc1[mt][nt][0] + bv.x);
                float vy0 = sspf(acc1[mt][nt][1] + bv.y);
                float vx1 = sspf(acc1[mt][nt][2] + bv.x);
                float vy1 = sspf(acc1[mt][nt][3] + bv.y);
                *(__nv_bfloat162*)(sT + r0 * 136 + cc) = __floats2bfloat162_rn(vx0, vy0);
                *(__nv_bfloat162*)(sT + r1 * 136 + cc) = __floats2bfloat162_rn(vx1, vy1);
            }
        }
    }
    __syncthreads();

    // ======== stage 2: hn = t @ Wl + bl + h ========
    float acc2[2][8][4] = {};
    ldg_w(cWl + SLOT_ELEMS, wreg, tid);
    mma_half<8>(sT, 136, 0, sWhi0, sWlo0, wm, wn, g, tg, acc2);
    sts_w(wreg, sWhi1, tid);
    __syncthreads();

    ldg_w(cW3, wreg, tid);
    mma_half<8>(sT, 136, 1, sWhi1, sWlo1, wm, wn, g, tg, acc2);
    sts_w(wreg, sWhi0, tid);
    {
#pragma unroll
        for (int mt = 0; mt < 2; mt++) {
            int r0 = wm * 32 + mt * 16 + g;
            int r1 = r0 + 8;
            float* h0p = h + (size_t)(row0 + r0) * 128;
            float* h1p = h + (size_t)(row0 + r1) * 128;
#pragma unroll
            for (int nt = 0; nt < 8; nt++) {
                int cc = wn * 64 + nt * 8 + tg * 2;
                float2 bv = *(const float2*)(bl + cc);
                float2 e0 = *(const float2*)(h0p + cc);
                float2 e1 = *(const float2*)(h1p + cc);
                float vx0 = acc2[mt][nt][0] + bv.x + e0.x;
                float vy0 = acc2[mt][nt][1] + bv.y + e0.y;
                float vx1 = acc2[mt][nt][2] + bv.x + e1.x;
                float vy1 = acc2[mt][nt][3] + bv.y + e1.y;
                *(float2*)(h0p + cc) = make_float2(vx0, vy0);
                *(float2*)(h1p + cc) = make_float2(vx1, vy1);
                *(__nv_bfloat162*)(sHn + r0 * 136 + cc) = __floats2bfloat162_rn(vx0, vy0);
                *(__nv_bfloat162*)(sHn + r1 * 136 + cc) = __floats2bfloat162_rn(vx1, vy1);
            }
        }
    }
    __syncthreads();

    // ======== stage 3: next x or readout ========
    if (!LAST) {
        float acc3[2][8][4] = {};
        ldg_w(cW3 + SLOT_ELEMS, wreg, tid);
        mma_half<8>(sHn, 136, 0, sWhi0, sWlo0, wm, wn, g, tg, acc3);
        sts_w(wreg, sWhi1, tid);
        __syncthreads();
        mma_half<8>(sHn, 136, 1, sWhi1, sWlo1, wm, wn, g, tg, acc3);
#pragma unroll
        for (int mt = 0; mt < 2; mt++) {
            int r0 = row0 + wm * 32 + mt * 16 + g;
            int r1 = r0 + 8;
#pragma unroll
            for (int nt = 0; nt < 8; nt++) {
                int cc = wn * 64 + nt * 8 + tg * 2;
                *(__nv_bfloat162*)(xb + (size_t)r0 * 128 + cc) =
                    __floats2bfloat162_rn(acc3[mt][nt][0], acc3[mt][nt][1]);
                *(__nv_bfloat162*)(xb + (size_t)r1 * 128 + cc) =
                    __floats2bfloat162_rn(acc3[mt][nt][2], acc3[mt][nt][3]);
            }
        }
    } else {
        float acc3[2][4][4] = {};
        ldg_w(cW3 + SLOT_ELEMS, wreg, tid);
        mma_half<4>(sHn, 136, 0, sWhi0, sWlo0, wm, wn, g, tg, acc3);
        sts_w(wreg, sWhi1, tid);
        __syncthreads();
        mma_half<4>(sHn, 136, 1, sWhi1, sWlo1, wm, wn, g, tg, acc3);
        float v = 0.0f;
#pragma unroll
        for (int mt = 0; mt < 2; mt++) {
#pragma unroll
            for (int nt = 0; nt < 4; nt++) {
                int cc = wn * 32 + nt * 8 + tg * 2;
                float2 bo = *(const float2*)(bo1 + cc);
                float2 w2 = *(const float2*)(Wo2 + cc);
                v += sspf(acc3[mt][nt][0] + bo.x) * w2.x + sspf(acc3[mt][nt][1] + bo.y) * w2.y;
                v += sspf(acc3[mt][nt][2] + bo.x) * w2.x + sspf(acc3[mt][nt][3] + bo.y) * w2.y;
            }
        }
#pragma unroll
        for (int off = 16; off > 0; off >>= 1)
            v += __shfl_xor_sync(0xFFFFFFFFu, v, off);
        if (lane == 0) atomicAdd(&g_sum, v);
    }
}

// ---------------- edge aggregation (dst-sorted, warp/node, nearest table) ----------------
__device__ __forceinline__ void edge_acc(const __nv_bfloat16* xb, const __nv_bfloat16* Tb,
                                         int pk, int lane, float4& acc) {
    int s = pk & 16383;
    int t0 = pk >> 14;
    uint2 xv = ((const uint2*)(xb + (size_t)s * 128))[lane];
    uint2 tv = ((const uint2*)(Tb + (size_t)t0 * 128))[lane];
    float2 x0 = __bfloat1622float2(*(__nv_bfloat162*)&xv.x);
    float2 x1 = __bfloat1622float2(*(__nv_bfloat162*)&xv.y);
    float2 f0 = __bfloat1622float2(*(__nv_bfloat162*)&tv.x);
    float2 f1 = __bfloat1622float2(*(__nv_bfloat162*)&tv.y);
    acc.x += x0.x * f0.x;
    acc.y += x0.y * f0.y;
    acc.z += x1.x * f1.x;
    acc.w += x1.y * f1.y;
}

__global__ void agg_kernel(const __nv_bfloat16* __restrict__ xb,
                           const __nv_bfloat16* __restrict__ Tb) {
    int warp = (blockIdx.x * blockDim.x + threadIdx.x) >> 5;
    int lane = threadIdx.x & 31;
    if (warp >= NN) return;
    int b = g_start[warp];
    int e = g_start[warp + 1];
    float4 acc = make_float4(0.f, 0.f, 0.f, 0.f);
    int j = b;
    for (; j + 4 <= e; j += 4) {
        int pk0 = g_perm[j],     pk1 = g_perm[j + 1];
        int pk2 = g_perm[j + 2], pk3 = g_perm[j + 3];
        edge_acc(xb, Tb, pk0, lane, acc);
        edge_acc(xb, Tb, pk1, lane, acc);
        edge_acc(xb, Tb, pk2, lane, acc);
        edge_acc(xb, Tb, pk3, lane, acc);
    }
    for (; j < e; j++) edge_acc(xb, Tb, g_perm[j], lane, acc);
    __nv_bfloat162 o0 = __floats2bfloat162_rn(acc.x, acc.y);
    __nv_bfloat162 o1 = __floats2bfloat162_rn(acc.z, acc.w);
    uint2 ov;
    ov.x = *(uint32_t*)&o0;
    ov.y = *(uint32_t*)&o1;
    ((uint2*)(g_aggb + (size_t)warp * 128))[lane] = ov;
}

__global__ void final_kernel(float* __restrict__ out, const float* __restrict__ bo2) {
    float v = g_sum + (float)NN * bo2[0];
    out[0] = fmaxf(v, 0.0f);
}

// ---------------- launch ----------------
extern "C" void kernel_launch(void* const* d_in, const int* in_sizes, int n_in,
                              void* d_out, int out_size) {
    const int*   z    = (const int*)d_in[0];
    const float* pos  = (const float*)d_in[1];
    const int*   ei   = (const int*)d_in[2];
    const float* emb  = (const float*)d_in[3];
    const float* Wf1  = (const float*)d_in[4];
    const float* bf1  = (const float*)d_in[5];
    const float* Wf2  = (const float*)d_in[6];
    const float* bf2  = (const float*)d_in[7];
    const float* Wl1  = (const float*)d_in[8];
    const float* Wl2  = (const float*)d_in[9];
    const float* bl2  = (const float*)d_in[10];
    const float* Wl   = (const float*)d_in[11];
    const float* bl   = (const float*)d_in[12];
    const float* Wo1  = (const float*)d_in[13];
    const float* bo1  = (const float*)d_in[14];
    const float* Wo2  = (const float*)d_in[15];
    const float* bo2  = (const float*)d_in[16];
    float* out = (float*)d_out;

    float *p_h;
    __nv_bfloat16 *p_hb, *p_xb, *p_aggb, *p_Tb, *p_Wc;
    cudaGetSymbolAddress((void**)&p_h,    g_h);
    cudaGetSymbolAddress((void**)&p_hb,   g_hb);
    cudaGetSymbolAddress((void**)&p_xb,   g_xb);
    cudaGetSymbolAddress((void**)&p_aggb, g_aggb);
    cudaGetSymbolAddress((void**)&p_Tb,   g_Tb);
    cudaGetSymbolAddress((void**)&p_Wc,   g_Wc);

    const int FUSED_SMEM = (4 * 128 * 72 + 2 * 128 * 136) * (int)sizeof(__nv_bfloat16);
    const int TABLE_SMEM = (5 * 128 * 72 + 128 * 136) * (int)sizeof(__nv_bfloat16);
    cudaFuncSetAttribute(fused_update<false>, cudaFuncAttributeMaxDynamicSharedMemorySize, FUSED_SMEM);
    cudaFuncSetAttribute(fused_update<true>,  cudaFuncAttributeMaxDynamicSharedMemorySize, FUSED_SMEM);
    cudaFuncSetAttribute(tableT_kernel, cudaFuncAttributeMaxDynamicSharedMemorySize, TABLE_SMEM);

    // --- weight preconversion (independent; head of graph) ---
    convW_kernel<<<NSLOT, 256>>>(Wl2, Wl, Wl1, Wo1, Wf1, Wf2);

    // --- edge prep + dst sort ---
    zero_kernel<<<NN / 256, 256>>>();
    prep_kernel<<<EE / 256, 256>>>(pos, ei);
    scan_kernel<<<1, 1024>>>();
    scatter_kernel<<<EE / 256, 256>>>(ei);
    emb_kernel<<<NN * HID / 256, 256>>>(z, emb);

    // --- filter tables, all-MMA (batched over 6 interactions) ---
    tableT_kernel<<<dim3(NTAB / 128, NINTER), 256, TABLE_SMEM>>>(bf1, bf2);

    // --- first x = h @ Wl1[0] ---
    gemm_x0<<<NN / 128, 256>>>(p_hb, p_xb);

    // --- interaction blocks: agg + fused pipelined update ---
    for (int i = 0; i < NINTER; i++) {
        agg_kernel<<<NN / 8, 256>>>(p_xb, p_Tb + (size_t)i * NTAB * HID);
        const __nv_bfloat16* cWl2 = p_Wc + (size_t)(2 * i) * SLOT_ELEMS;
        const __nv_bfloat16* cWl  = p_Wc + (size_t)(12 + 2 * i) * SLOT_ELEMS;
        if (i < NINTER - 1) {
            const __nv_bfloat16* cW3 = p_Wc + (size_t)(24 + 2 * (i + 1)) * SLOT_ELEMS;
            fused_update<false><<<NN / 128, 256, FUSED_SMEM>>>(
                p_aggb, p_h,
                cWl2, bl2 + (size_t)i * HID,
                cWl,  bl  + (size_t)i * HID,
                cW3, nullptr, nullptr, p_xb);
        } else {
            const __nv_bfloat16* cW3 = p_Wc + (size_t)36 * SLOT_ELEMS;
            fused_update<true><<<NN / 128, 256, FUSED_SMEM>>>(
                p_aggb, p_h,
                cWl2, bl2 + (size_t)i * HID,
                cWl,  bl  + (size_t)i * HID,
                cW3, bo1, Wo2, nullptr);
        }
    }

    final_kernel<<<1, 1>>>(out, bo2);
}

// round 16
// speedup vs baseline: 1.5556x; 1.0547x over previous
#include <cuda_runtime.h>
#include <cuda_bf16.h>
#include <math.h>
#include <cstdint>

#define NN      16384
#define EE      262144
#define HID     128
#define NGAUSS  50
#define NINTER  6
#define NTAB    8192
#define DMAX    8.6610f
#define DELTA   (DMAX / (float)(NTAB - 1))
#define GSPACE  (10.0f / 49.0f)
#define GCOEFF  (-0.5f / (GSPACE * GSPACE))
#define LOG2F_C 0.69314718055994530942f
#define PI_O10  0.31415926535897932f

#define SLOT_ELEMS 18432   // one 64x128 chunk: hi[128*72] + lo[128*72] bf16
#define NSLOT 56

// ---------------- device scratch ----------------
__device__ float g_d[EE];
__device__ int   g_perm[EE];               // packed (t0 << 14) | src
__device__ int   g_start[NN];
__device__ int   g_len[NN];
__device__ int   g_cnt[NN];
__device__ int   g_total;
__device__ float g_h[NN * HID];            // fp32 residual stream
__device__ __nv_bfloat16 g_hb[NN * HID];   // bf16 shadow (first x GEMM)
__device__ __nv_bfloat16 g_xb[NN * HID];
__device__ __nv_bfloat16 g_aggb[NN * HID];
__device__ __nv_bfloat16 g_Tb[NINTER * NTAB * HID];
__device__ __nv_bfloat16 g_Wc[NSLOT * SLOT_ELEMS];   // preconverted weights
__device__ float g_sum;

__device__ __forceinline__ float sspf(float x) {
    float sp = (x > 15.0f) ? x : log1pf(expf(x));
    return sp - LOG2F_C;
}

// ---------------- prep kernels ----------------
__global__ void zero_kernel() {
    int i = blockIdx.x * blockDim.x + threadIdx.x;
    if (i < NN) g_cnt[i] = 0;
    if (i == 0) { g_sum = 0.0f; g_total = 0; }
}

__global__ void prep_kernel(const float* __restrict__ pos, const int* __restrict__ ei) {
    int e = blockIdx.x * blockDim.x + threadIdx.x;
    if (e >= EE) return;
    int s = ei[e];
    int t = ei[EE + e];
    float dx = pos[3 * s + 0] - pos[3 * t + 0];
    float dy = pos[3 * s + 1] - pos[3 * t + 1];
    float dz = pos[3 * s + 2] - pos[3 * t + 2];
    g_d[e] = sqrtf(dx * dx + dy * dy + dz * dz);
    atomicAdd(&g_cnt[t], 1);
}

// multi-block scan: each block scans 256 counts, claims range via one atomicAdd.
// Segment ORDER across blocks is nondeterministic but contiguity + start/len are exact.
__global__ void scan_kernel() {
    __shared__ int warpsum[8];
    __shared__ int sbase;
    const int tid = threadIdx.x;
    const int lane = tid & 31, wid = tid >> 5;
    const int node = blockIdx.x * 256 + tid;

    int c = g_cnt[node];
    int ps = c;
#pragma unroll
    for (int off = 1; off < 32; off <<= 1) {
        int v = __shfl_up_sync(0xFFFFFFFFu, ps, off);
        if (lane >= off) ps += v;
    }
    if (lane == 31) warpsum[wid] = ps;
    __syncthreads();
    if (wid == 0) {
        int ws = (lane < 8) ? warpsum[lane] : 0;
#pragma unroll
        for (int off = 1; off < 8; off <<= 1) {
            int v = __shfl_up_sync(0xFFFFFFFFu, ws, off);
            if (lane >= off) ws += v;
        }
        if (lane < 8) warpsum[lane] = ws;
    }
    __syncthreads();
    int excl = ps - c + ((wid > 0) ? warpsum[wid - 1] : 0);
    if (tid == 0) sbase = atomicAdd(&g_total, warpsum[7]);
    __syncthreads();
    int start = sbase + excl;
    g_start[node] = start;
    g_len[node] = c;
    g_cnt[node] = start;   // cursor init for scatter
}

__global__ void scatter_kernel(const int* __restrict__ ei) {
    int e = blockIdx.x * blockDim.x + threadIdx.x;
    if (e >= EE) return;
    int t = ei[EE + e];
    int s = ei[e];
    float f = g_d[e] * (1.0f / DELTA);
    int t0 = (int)(f + 0.5f);              // nearest table entry
    t0 = min(t0, NTAB - 1);
    int p = atomicAdd(&g_cnt[t], 1);
    g_perm[p] = (t0 << 14) | s;
}

__global__ void emb_kernel(const int* __restrict__ z, const float* __restrict__ emb) {
    int idx = blockIdx.x * blockDim.x + threadIdx.x;
    if (idx >= NN * HID) return;
    int n = idx >> 7, c = idx & 127;
    float v = emb[z[n] * HID + c];
    g_h[idx] = v;
    g_hb[idx] = __float2bfloat16(v);
}

// ---------------- weight preconversion: fp32 -> hi/lo bf16 in fragment layout ----------------
// slot map: 0..11 Wl2[i](kh), 12..23 Wl[i](kh), 24..35 Wl1[i](kh),
//           36..37 Wo1(kh, NC=64), 38..43 Wf1[i](padded K), 44..55 Wf2[i](kh)
__global__ void convW_kernel(const float* __restrict__ Wl2, const float* __restrict__ Wl,
                             const float* __restrict__ Wl1, const float* __restrict__ Wo1,
                             const float* __restrict__ Wf1, const float* __restrict__ Wf2) {
    int slot = blockIdx.x;
    int tid = threadIdx.x;
    __nv_bfloat16* dst = g_Wc + (size_t)slot * SLOT_ELEMS;
    const float* src;
    int kh, NC = 128;
    bool padK = false;
    if (slot < 12)      { src = Wl2 + (size_t)(slot >> 1) * 16384; kh = slot & 1; }
    else if (slot < 24) { src = Wl  + (size_t)((slot - 12) >> 1) * 16384; kh = slot & 1; }
    else if (slot < 36) { src = Wl1 + (size_t)((slot - 24) >> 1) * 16384; kh = slot & 1; }
    else if (slot < 38) { src = Wo1; kh = slot - 36; NC = 64; }
    else if (slot < 44) { src = Wf1 + (size_t)(slot - 38) * NGAUSS * 128; kh = 0; padK = true; }
    else                { src = Wf2 + (size_t)((slot - 44) >> 1) * 16384; kh = slot & 1; }

    for (int flat = tid; flat < 128 * 64; flat += 256) {
        int n = flat >> 6, kp = flat & 63;
        int krow = kh * 64 + kp;
        float v = 0.0f;
        if (n < NC && !(padK && krow >= NGAUSS))
            v = src[(size_t)krow * NC + n];
        __nv_bfloat16 h = __float2bfloat16(v);
        dst[n * 72 + kp] = h;
        dst[9216 + n * 72 + kp] = __float2bfloat16(v - __bfloat162float(h));
    }
}

// ---------------- MMA helpers ----------------
#define MMA16816(d, a, b0, b1) \
    asm volatile("mma.sync.aligned.m16n8k16.row.col.f32.bf16.bf16.f32 " \
        "{%0,%1,%2,%3}, {%4,%5,%6,%7}, {%8,%9}, {%0,%1,%2,%3};" \
        : "+f"((d)[0]), "+f"((d)[1]), "+f"((d)[2]), "+f"((d)[3]) \
        : "r"((a)[0]), "r"((a)[1]), "r"((a)[2]), "r"((a)[3]), "r"(b0), "r"(b1))

// ---------------- preconverted-weight staging (pure copy) ----------------
__device__ __forceinline__ void ldg_w(const __nv_bfloat16* __restrict__ src,
                                      uint4* wreg, int tid) {
    const uint4* s = (const uint4*)src;
#pragma unroll
    for (int i = 0; i < 9; i++) wreg[i] = s[tid + i * 256];
}
__device__ __forceinline__ void sts_w(const uint4* wreg, __nv_bfloat16* dsthi, int tid) {
    uint4* d = (uint4*)dsthi;
#pragma unroll
    for (int i = 0; i < 9; i++) d[tid + i * 256] = wreg[i];
}

template <int NT>
__device__ __forceinline__ void mma_half(
    const __nv_bfloat16* __restrict__ A, int lda, int kh,
    const __nv_bfloat16* hi, const __nv_bfloat16* lo,
    int wm, int wn, int g, int tg, float acc[2][NT][4])
{
    const __nv_bfloat16* rp0 = A + (wm * 32 + g) * lda;
    const int colbase = wn * (NT * 8);
#pragma unroll
    for (int ks = 0; ks < 4; ks++) {
        int kc = kh * 64 + ks * 16 + tg * 2;
        uint32_t af[2][4];
#pragma unroll
        for (int mt = 0; mt < 2; mt++) {
            const __nv_bfloat16* rp = rp0 + mt * 16 * lda;
            af[mt][0] = *(const uint32_t*)(rp + kc);
            af[mt][1] = *(const uint32_t*)(rp + 8 * lda + kc);
            af[mt][2] = *(const uint32_t*)(rp + kc + 8);
            af[mt][3] = *(const uint32_t*)(rp + 8 * lda + kc + 8);
        }
        int c = ks * 16 + tg * 2;
#pragma unroll
        for (int nt = 0; nt < NT; nt++) {
            int n = colbase + nt * 8 + g;
            uint32_t bh0 = *(const uint32_t*)(hi + n * 72 + c);
            uint32_t bh1 = *(const uint32_t*)(hi + n * 72 + c + 8);
            uint32_t bl0 = *(const uint32_t*)(lo + n * 72 + c);
            uint32_t bl1 = *(const uint32_t*)(lo + n * 72 + c + 8);
#pragma unroll
            for (int mt = 0; mt < 2; mt++) {
                MMA16816(acc[mt][nt], af[mt], bh0, bh1);
                MMA16816(acc[mt][nt], af[mt], bl0, bl1);
            }
        }
    }
}

// ---------------- filter-table builder: ea->GEMM->ssp->GEMM->cutoff ----------------
__global__ __launch_bounds__(256) void tableT_kernel(
    const float* __restrict__ bf1, const float* __restrict__ bf2)
{
    extern __shared__ __align__(16) char smem_raw[];
    __nv_bfloat16* sWhi0 = (__nv_bfloat16*)smem_raw;     // 128*72
    __nv_bfloat16* sWlo0 = sWhi0 + 128 * 72;
    __nv_bfloat16* sWhi1 = sWlo0 + 128 * 72;
    __nv_bfloat16* sWlo1 = sWhi1 + 128 * 72;
    __nv_bfloat16* sEa   = sWlo1 + 128 * 72;             // 128*72 (K=64 padded)
    __nv_bfloat16* sT    = sEa + 128 * 72;               // 128*136

    const int tid = threadIdx.x;
    const int w = tid >> 5, lane = tid & 31;
    const int wm = w >> 1, wn = w & 1;
    const int g = lane >> 2, tg = lane & 3;
    const int inter = blockIdx.y;
    const int row0 = blockIdx.x * 128;

    const __nv_bfloat16* cWf1 = g_Wc + (size_t)(38 + inter) * SLOT_ELEMS;
    const __nv_bfloat16* cWf2 = g_Wc + (size_t)(44 + 2 * inter) * SLOT_ELEMS;
    const float* b1 = bf1 + (size_t)inter * HID;
    const float* b2 = bf2 + (size_t)inter * HID;

    // Gaussian rows (bf16, K padded to 64)
    for (int idx = tid; idx < 128 * 64; idx += 256) {
        int r = idx >> 6, k = idx & 63;
        float v = 0.0f;
        if (k < NGAUSS) {
            float u = (float)(row0 + r) * DELTA - (float)k * GSPACE;
            v = expf(GCOEFF * u * u);
        }
        sEa[r * 72 + k] = __float2bfloat16(v);
    }

    uint4 wreg[9];
    ldg_w(cWf1, wreg, tid);
    sts_w(wreg, sWhi0, tid);
    __syncthreads();

    // ---- GEMM1: H = ssp(ea @ Wf1 + bf1) -> sT ----
    {
        float acc1[2][8][4] = {};
        ldg_w(cWf2, wreg, tid);
        mma_half<8>(sEa, 72, 0, sWhi0, sWlo0, wm, wn, g, tg, acc1);
        sts_w(wreg, sWhi1, tid);
#pragma unroll
        for (int mt = 0; mt < 2; mt++) {
            int r0 = wm * 32 + mt * 16 + g;
            int r1 = r0 + 8;
#pragma unroll
            for (int nt = 0; nt < 8; nt++) {
                int cc = wn * 64 + nt * 8 + tg * 2;
                float2 bv = *(const float2*)(b1 + cc);
                float vx0 = sspf(acc1[mt][nt][0] + bv.x);
                float vy0 = sspf(acc1[mt][nt][1] + bv.y);
                float vx1 = sspf(acc1[mt][nt][2] + bv.x);
                float vy1 = sspf(acc1[mt][nt][3] + bv.y);
                *(__nv_bfloat162*)(sT + r0 * 136 + cc) = __floats2bfloat162_rn(vx0, vy0);
                *(__nv_bfloat162*)(sT + r1 * 136 + cc) = __floats2bfloat162_rn(vx1, vy1);
            }
        }
    }
    __syncthreads();

    // ---- GEMM2: T = (H @ Wf2 + bf2) * cutoff(row) -> g_Tb ----
    {
        float acc2[2][8][4] = {};
        ldg_w(cWf2 + SLOT_ELEMS, wreg, tid);
        mma_half<8>(sT, 136, 0, sWhi1, sWlo1, wm, wn, g, tg, acc2);
        sts_w(wreg, sWhi0, tid);
        __syncthreads();
        mma_half<8>(sT, 136, 1, sWhi0, sWlo0, wm, wn, g, tg, acc2);
        __nv_bfloat16* outB = g_Tb + (size_t)inter * NTAB * HID;
#pragma unroll
        for (int mt = 0; mt < 2; mt++) {
            int r0 = row0 + wm * 32 + mt * 16 + g;
            int r1 = r0 + 8;
            float s0 = 0.5f * (cosf((float)r0 * DELTA * PI_O10) + 1.0f);
            float s1 = 0.5f * (cosf((float)r1 * DELTA * PI_O10) + 1.0f);
#pragma unroll
            for (int nt = 0; nt < 8; nt++) {
                int cc = wn * 64 + nt * 8 + tg * 2;
                float2 bv = *(const float2*)(b2 + cc);
                float vx0 = (acc2[mt][nt][0] + bv.x) * s0;
                float vy0 = (acc2[mt][nt][1] + bv.y) * s0;
                float vx1 = (acc2[mt][nt][2] + bv.x) * s1;
                float vy1 = (acc2[mt][nt][3] + bv.y) * s1;
                *(__nv_bfloat162*)(outB + (size_t)r0 * 128 + cc) = __floats2bfloat162_rn(vx0, vy0);
                *(__nv_bfloat162*)(outB + (size_t)r1 * 128 + cc) = __floats2bfloat162_rn(vx1, vy1);
            }
        }
    }
}

// ---------------- standalone GEMM: x0 = hb @ Wl1[0] ----------------
__global__ __launch_bounds__(256) void gemm_x0(
    const __nv_bfloat16* __restrict__ A, __nv_bfloat16* __restrict__ outB)
{
    __shared__ __nv_bfloat16 sBhi[2 * 128 * 72];   // hi + lo contiguous

    const int tid = threadIdx.x;
    const int w = tid >> 5, lane = tid & 31;
    const int wm = w >> 1, wn = w & 1;
    const int g = lane >> 2, tg = lane & 3;
    const int row0 = blockIdx.x * 128;

    const __nv_bfloat16* cW = g_Wc + (size_t)24 * SLOT_ELEMS;   // Wl1[0] kh0/kh1
    __nv_bfloat16* sBlo = sBhi + 128 * 72;

    float acc[2][8][4] = {};
    const __nv_bfloat16* aBase = A + (size_t)row0 * 128;
    uint4 wreg[9];

    ldg_w(cW, wreg, tid);
    sts_w(wreg, sBhi, tid);
    __syncthreads();
    ldg_w(cW + SLOT_ELEMS, wreg, tid);
    mma_half<8>(aBase, 128, 0, sBhi, sBlo, wm, wn, g, tg, acc);
    __syncthreads();
    sts_w(wreg, sBhi, tid);
    __syncthreads();
    mma_half<8>(aBase, 128, 1, sBhi, sBlo, wm, wn, g, tg, acc);

#pragma unroll
    for (int mt = 0; mt < 2; mt++) {
        int r0 = row0 + wm * 32 + mt * 16 + g;
        int r1 = r0 + 8;
#pragma unroll
        for (int nt = 0; nt < 8; nt++) {
            int cc = wn * 64 + nt * 8 + tg * 2;
            *(__nv_bfloat162*)(outB + (size_t)r0 * 128 + cc) =
                __floats2bfloat162_rn(acc[mt][nt][0], acc[mt][nt][1]);
            *(__nv_bfloat162*)(outB + (size_t)r1 * 128 + cc) =
                __floats2bfloat162_rn(acc[mt][nt][2], acc[mt][nt][3]);
        }
    }
}

// ---------------- fused interaction update: 3 chained GEMMs, copy-staged weights ----------------
template <bool LAST>
__global__ __launch_bounds__(256) void fused_update(
    const __nv_bfloat16* __restrict__ aggb,
    float* __restrict__ h,
    const __nv_bfloat16* __restrict__ cWl2, const float* __restrict__ bl2,
    const __nv_bfloat16* __restrict__ cWl,  const float* __restrict__ bl,
    const __nv_bfloat16* __restrict__ cW3,
    const float* __restrict__ bo1, const float* __restrict__ Wo2,
    __nv_bfloat16* __restrict__ xb)
{
    extern __shared__ __align__(16) char smem_raw[];
    __nv_bfloat16* sWhi0 = (__nv_bfloat16*)smem_raw;     // 128*72
    __nv_bfloat16* sWlo0 = sWhi0 + 128 * 72;
    __nv_bfloat16* sWhi1 = sWlo0 + 128 * 72;
    __nv_bfloat16* sWlo1 = sWhi1 + 128 * 72;
    __nv_bfloat16* sT    = sWlo1 + 128 * 72;             // 128*136
    __nv_bfloat16* sHn   = sT + 128 * 136;               // 128*136

    const int tid = threadIdx.x;
    const int w = tid >> 5, lane = tid & 31;
    const int wm = w >> 1, wn = w & 1;
    const int g = lane >> 2, tg = lane & 3;
    const int row0 = blockIdx.x * 128;

    uint4 wreg[9];
    const __nv_bfloat16* aggA = aggb + (size_t)row0 * 128;

    // preload (Wl2, kh0)
    ldg_w(cWl2, wreg, tid);
    sts_w(wreg, sWhi0, tid);
    __syncthreads();

    // ======== stage 1: t = ssp(aggb @ Wl2 + bl2) ========
    float acc1[2][8][4] = {};
    ldg_w(cWl2 + SLOT_ELEMS, wreg, tid);
    mma_half<8>(aggA, 128, 0, sWhi0, sWlo0, wm, wn, g, tg, acc1);
    sts_w(wreg, sWhi1, tid);
    __syncthreads();

    ldg_w(cWl, wreg, tid);
    mma_half<8>(aggA, 128, 1, sWhi1, sWlo1, wm, wn, g, tg, acc1);
    sts_w(wreg, sWhi0, tid);
    {
#pragma unroll
        for (int mt = 0; mt < 2; mt++) {
            int r0 = wm * 32 + mt * 16 + g;
            int r1 = r0 + 8;
#pragma unroll
            for (int nt = 0; nt < 8; nt++) {
                int cc = wn * 64 + nt * 8 + tg * 2;
                float2 bv = *(const float2*)(bl2 + cc);
                float vx0 = sspf(acc1[mt][nt][0] + bv.x);
                float vy0 = sspf(acc1[mt][nt][1] + bv.y);
                float vx1 = sspf(acc1[mt][nt][2] + bv.x);
                float vy1 = sspf(acc1[mt][nt][3] + bv.y);
                *(__nv_bfloat162*)(sT + r0 * 136 + cc) = __floats2bfloat162_rn(vx0, vy0);
                *(__nv_bfloat162*)(sT + r1 * 136 + cc) = __floats2bfloat162_rn(vx1, vy1);
            }
        }
    }
    __syncthreads();

    // ======== stage 2: hn = t @ Wl + bl + h ========
    float acc2[2][8][4] = {};
    ldg_w(cWl + SLOT_ELEMS, wreg, tid);
    mma_half<8>(sT, 136, 0, sWhi0, sWlo0, wm, wn, g, tg, acc2);
    sts_w(wreg, sWhi1, tid);
    __syncthreads();

    ldg_w(cW3, wreg, tid);
    mma_half<8>(sT, 136, 1, sWhi1, sWlo1, wm, wn, g, tg, acc2);
    sts_w(wreg, sWhi0, tid);
    {
#pragma unroll
        for (int mt = 0; mt < 2; mt++) {
            int r0 = wm * 32 + mt * 16 + g;
            int r1 = r0 + 8;
            float* h0p = h + (size_t)(row0 + r0) * 128;
            float* h1p = h + (size_t)(row0 + r1) * 128;
#pragma unroll
            for (int nt = 0; nt < 8; nt++) {
                int cc = wn * 64 + nt * 8 + tg * 2;
                float2 bv = *(const float2*)(bl + cc);
                float2 e0 = *(const float2*)(h0p + cc);
                float2 e1 = *(const float2*)(h1p + cc);
                float vx0 = acc2[mt][nt][0] + bv.x + e0.x;
                float vy0 = acc2[mt][nt][1] + bv.y + e0.y;
                float vx1 = acc2[mt][nt][2] + bv.x + e1.x;
                float vy1 = acc2[mt][nt][3] + bv.y + e1.y;
                *(float2*)(h0p + cc) = make_float2(vx0, vy0);
                *(float2*)(h1p + cc) = make_float2(vx1, vy1);
                *(__nv_bfloat162*)(sHn + r0 * 136 + cc) = __floats2bfloat162_rn(vx0, vy0);
                *(__nv_bfloat162*)(sHn + r1 * 136 + cc) = __floats2bfloat162_rn(vx1, vy1);
            }
        }
    }
    __syncthreads();

    // ======== stage 3: next x or readout ========
    if (!LAST) {
        float acc3[2][8][4] = {};
        ldg_w(cW3 + SLOT_ELEMS, wreg, tid);
        mma_half<8>(sHn, 136, 0, sWhi0, sWlo0, wm, wn, g, tg, acc3);
        sts_w(wreg, sWhi1, tid);
        __syncthreads();
        mma_half<8>(sHn, 136, 1, sWhi1, sWlo1, wm, wn, g, tg, acc3);
#pragma unroll
        for (int mt = 0; mt < 2; mt++) {
            int r0 = row0 + wm * 32 + mt * 16 + g;
            int r1 = r0 + 8;
#pragma unroll
            for (int nt = 0; nt < 8; nt++) {
                int cc = wn * 64 + nt * 8 + tg * 2;
                *(__nv_bfloat162*)(xb + (size_t)r0 * 128 + cc) =
                    __floats2bfloat162_rn(acc3[mt][nt][0], acc3[mt][nt][1]);
                *(__nv_bfloat162*)(xb + (size_t)r1 * 128 + cc) =
                    __floats2bfloat162_rn(acc3[mt][nt][2], acc3[mt][nt][3]);
            }
        }
    } else {
        float acc3[2][4][4] = {};
        ldg_w(cW3 + SLOT_ELEMS, wreg, tid);
        mma_half<4>(sHn, 136, 0, sWhi0, sWlo0, wm, wn, g, tg, acc3);
        sts_w(wreg, sWhi1, tid);
        __syncthreads();
        mma_half<4>(sHn, 136, 1, sWhi1, sWlo1, wm, wn, g, tg, acc3);
        float v = 0.0f;
#pragma unroll
        for (int mt = 0; mt < 2; mt++) {
#pragma unroll
            for (int nt = 0; nt < 4; nt++) {
                int cc = wn * 32 + nt * 8 + tg * 2;
                float2 bo = *(const float2*)(bo1 + cc);
                float2 w2 = *(const float2*)(Wo2 + cc);
                v += sspf(acc3[mt][nt][0] + bo.x) * w2.x + sspf(acc3[mt][nt][1] + bo.y) * w2.y;
                v += sspf(acc3[mt][nt][2] + bo.x) * w2.x + sspf(acc3[mt][nt][3] + bo.y) * w2.y;
            }
        }
#pragma unroll
        for (int off = 16; off > 0; off >>= 1)
            v += __shfl_xor_sync(0xFFFFFFFFu, v, off);
        if (lane == 0) atomicAdd(&g_sum, v);
    }
}

// ---------------- edge aggregation (dst-sorted, warp/node, nearest table) ----------------
__device__ __forceinline__ void edge_acc(const __nv_bfloat16* xb, const __nv_bfloat16* Tb,
                                         int pk, int lane, float4& acc) {
    int s = pk & 16383;
    int t0 = pk >> 14;
    uint2 xv = ((const uint2*)(xb + (size_t)s * 128))[lane];
    uint2 tv = ((const uint2*)(Tb + (size_t)t0 * 128))[lane];
    float2 x0 = __bfloat1622float2(*(__nv_bfloat162*)&xv.x);
    float2 x1 = __bfloat1622float2(*(__nv_bfloat162*)&xv.y);
    float2 f0 = __bfloat1622float2(*(__nv_bfloat162*)&tv.x);
    float2 f1 = __bfloat1622float2(*(__nv_bfloat162*)&tv.y);
    acc.x += x0.x * f0.x;
    acc.y += x0.y * f0.y;
    acc.z += x1.x * f1.x;
    acc.w += x1.y * f1.y;
}

__global__ void agg_kernel(const __nv_bfloat16* __restrict__ xb,
                           const __nv_bfloat16* __restrict__ Tb) {
    int warp = (blockIdx.x * blockDim.x + threadIdx.x) >> 5;
    int lane = threadIdx.x & 31;
    if (warp >= NN) return;
    int b = g_start[warp];
    int e = b + g_len[warp];
    float4 acc = make_float4(0.f, 0.f, 0.f, 0.f);
    int j = b;
    for (; j + 4 <= e; j += 4) {
        int pk0 = g_perm[j],     pk1 = g_perm[j + 1];
        int pk2 = g_perm[j + 2], pk3 = g_perm[j + 3];
        edge_acc(xb, Tb, pk0, lane, acc);
        edge_acc(xb, Tb, pk1, lane, acc);
        edge_acc(xb, Tb, pk2, lane, acc);
        edge_acc(xb, Tb, pk3, lane, acc);
    }
    for (; j < e; j++) edge_acc(xb, Tb, g_perm[j], lane, acc);
    __nv_bfloat162 o0 = __floats2bfloat162_rn(acc.x, acc.y);
    __nv_bfloat162 o1 = __floats2bfloat162_rn(acc.z, acc.w);
    uint2 ov;
    ov.x = *(uint32_t*)&o0;
    ov.y = *(uint32_t*)&o1;
    ((uint2*)(g_aggb + (size_t)warp * 128))[lane] = ov;
}

__global__ void final_kernel(float* __restrict__ out, const float* __restrict__ bo2) {
    float v = g_sum + (float)NN * bo2[0];
    out[0] = fmaxf(v, 0.0f);
}

// ---------------- launch ----------------
extern "C" void kernel_launch(void* const* d_in, const int* in_sizes, int n_in,
                              void* d_out, int out_size) {
    const int*   z    = (const int*)d_in[0];
    const float* pos  = (const float*)d_in[1];
    const int*   ei   = (const int*)d_in[2];
    const float* emb  = (const float*)d_in[3];
    const float* Wf1  = (const float*)d_in[4];
    const float* bf1  = (const float*)d_in[5];
    const float* Wf2  = (const float*)d_in[6];
    const float* bf2  = (const float*)d_in[7];
    const float* Wl1  = (const float*)d_in[8];
    const float* Wl2  = (const float*)d_in[9];
    const float* bl2  = (const float*)d_in[10];
    const float* Wl   = (const float*)d_in[11];
    const float* bl   = (const float*)d_in[12];
    const float* Wo1  = (const float*)d_in[13];
    const float* bo1  = (const float*)d_in[14];
    const float* Wo2  = (const float*)d_in[15];
    const float* bo2  = (const float*)d_in[16];
    float* out = (float*)d_out;

    float *p_h;
    __nv_bfloat16 *p_hb, *p_xb, *p_aggb, *p_Tb, *p_Wc;
    cudaGetSymbolAddress((void**)&p_h,    g_h);
    cudaGetSymbolAddress((void**)&p_hb,   g_hb);
    cudaGetSymbolAddress((void**)&p_xb,   g_xb);
    cudaGetSymbolAddress((void**)&p_aggb, g_aggb);
    cudaGetSymbolAddress((void**)&p_Tb,   g_Tb);
    cudaGetSymbolAddress((void**)&p_Wc,   g_Wc);

    const int FUSED_SMEM = (4 * 128 * 72 + 2 * 128 * 136) * (int)sizeof(__nv_bfloat16);
    const int TABLE_SMEM = (5 * 128 * 72 + 128 * 136) * (int)sizeof(__nv_bfloat16);
    cudaFuncSetAttribute(fused_update<false>, cudaFuncAttributeMaxDynamicSharedMemorySize, FUSED_SMEM);
    cudaFuncSetAttribute(fused_update<true>,  cudaFuncAttributeMaxDynamicSharedMemorySize, FUSED_SMEM);
    cudaFuncSetAttribute(tableT_kernel, cudaFuncAttributeMaxDynamicSharedMemorySize, TABLE_SMEM);

    // --- weight preconversion (independent; head of graph) ---
    convW_kernel<<<NSLOT, 256>>>(Wl2, Wl, Wl1, Wo1, Wf1, Wf2);

    // --- edge prep + dst sort ---
    zero_kernel<<<NN / 256, 256>>>();
    prep_kernel<<<EE / 256, 256>>>(pos, ei);
    scan_kernel<<<NN / 256, 256>>>();
    scatter_kernel<<<EE / 256, 256>>>(ei);
    emb_kernel<<<NN * HID / 256, 256>>>(z, emb);

    // --- filter tables, all-MMA (batched over 6 interactions) ---
    tableT_kernel<<<dim3(NTAB / 128, NINTER), 256, TABLE_SMEM>>>(bf1, bf2);

    // --- first x = h @ Wl1[0] ---
    gemm_x0<<<NN / 128, 256>>>(p_hb, p_xb);

    // --- interaction blocks: agg + fused pipelined update ---
    for (int i = 0; i < NINTER; i++) {
        agg_kernel<<<NN / 8, 256>>>(p_xb, p_Tb + (size_t)i * NTAB * HID);
        const __nv_bfloat16* cWl2 = p_Wc + (size_t)(2 * i) * SLOT_ELEMS;
        const __nv_bfloat16* cWl  = p_Wc + (size_t)(12 + 2 * i) * SLOT_ELEMS;
        if (i < NINTER - 1) {
            const __nv_bfloat16* cW3 = p_Wc + (size_t)(24 + 2 * (i + 1)) * SLOT_ELEMS;
            fused_update<false><<<NN / 128, 256, FUSED_SMEM>>>(
                p_aggb, p_h,
                cWl2, bl2 + (size_t)i * HID,
                cWl,  bl  + (size_t)i * HID,
                cW3, nullptr, nullptr, p_xb);
        } else {
            const __nv_bfloat16* cW3 = p_Wc + (size_t)36 * SLOT_ELEMS;
            fused_update<true><<<NN / 128, 256, FUSED_SMEM>>>(
                p_aggb, p_h,
                cWl2, bl2 + (size_t)i * HID,
                cWl,  bl  + (size_t)i * HID,
                cW3, bo1, Wo2, nullptr);
        }
    }

    final_kernel<<<1, 1>>>(out, bo2);
}

// round 17
// speedup vs baseline: 1.7614x; 1.1323x over previous
#include <cuda_runtime.h>
#include <cuda_bf16.h>
#include <math.h>
#include <cstdint>

#define NN      16384
#define EE      262144
#define HID     128
#define NGAUSS  50
#define NINTER  6
#define NTAB    8192
#define DMAX    8.6610f
#define DELTA   (DMAX / (float)(NTAB - 1))
#define GSPACE  (10.0f / 49.0f)
#define GCOEFF  (-0.5f / (GSPACE * GSPACE))
#define LOG2F_C 0.69314718055994530942f
#define PI_O10  0.31415926535897932f

#define SLOT_ELEMS 9216    // one 64x128 chunk: bf16 [n*72+kp]
#define NSLOT 56

// ---------------- device scratch ----------------
__device__ float g_d[EE];
__device__ int   g_perm[EE];               // packed (t0 << 14) | src
__device__ int   g_start[NN];
__device__ int   g_len[NN];
__device__ int   g_cnt[NN];
__device__ int   g_total;
__device__ float g_h[NN * HID];            // fp32 residual stream
__device__ __nv_bfloat16 g_hb[NN * HID];   // bf16 shadow (first x GEMM)
__device__ __nv_bfloat16 g_xb[NN * HID];
__device__ __nv_bfloat16 g_aggb[NN * HID];
__device__ __nv_bfloat16 g_Tb[NINTER * NTAB * HID];
__device__ __nv_bfloat16 g_Wc[NSLOT * SLOT_ELEMS];   // preconverted bf16 weights
__device__ float g_sum;

__device__ __forceinline__ float sspf(float x) {
    float sp = (x > 15.0f) ? x : log1pf(expf(x));
    return sp - LOG2F_C;
}

// ---------------- prep kernels ----------------
__global__ void zero_kernel() {
    int i = blockIdx.x * blockDim.x + threadIdx.x;
    if (i < NN) g_cnt[i] = 0;
    if (i == 0) { g_sum = 0.0f; g_total = 0; }
}

__global__ void prep_kernel(const float* __restrict__ pos, const int* __restrict__ ei) {
    int e = blockIdx.x * blockDim.x + threadIdx.x;
    if (e >= EE) return;
    int s = ei[e];
    int t = ei[EE + e];
    float dx = pos[3 * s + 0] - pos[3 * t + 0];
    float dy = pos[3 * s + 1] - pos[3 * t + 1];
    float dz = pos[3 * s + 2] - pos[3 * t + 2];
    g_d[e] = sqrtf(dx * dx + dy * dy + dz * dz);
    atomicAdd(&g_cnt[t], 1);
}

// multi-block scan: each block scans 256 counts, claims range via one atomicAdd.
__global__ void scan_kernel() {
    __shared__ int warpsum[8];
    __shared__ int sbase;
    const int tid = threadIdx.x;
    const int lane = tid & 31, wid = tid >> 5;
    const int node = blockIdx.x * 256 + tid;

    int c = g_cnt[node];
    int ps = c;
#pragma unroll
    for (int off = 1; off < 32; off <<= 1) {
        int v = __shfl_up_sync(0xFFFFFFFFu, ps, off);
        if (lane >= off) ps += v;
    }
    if (lane == 31) warpsum[wid] = ps;
    __syncthreads();
    if (wid == 0) {
        int ws = (lane < 8) ? warpsum[lane] : 0;
#pragma unroll
        for (int off = 1; off < 8; off <<= 1) {
            int v = __shfl_up_sync(0xFFFFFFFFu, ws, off);
            if (lane >= off) ws += v;
        }
        if (lane < 8) warpsum[lane] = ws;
    }
    __syncthreads();
    int excl = ps - c + ((wid > 0) ? warpsum[wid - 1] : 0);
    if (tid == 0) sbase = atomicAdd(&g_total, warpsum[7]);
    __syncthreads();
    int start = sbase + excl;
    g_start[node] = start;
    g_len[node] = c;
    g_cnt[node] = start;   // cursor init for scatter
}

__global__ void scatter_kernel(const int* __restrict__ ei) {
    int e = blockIdx.x * blockDim.x + threadIdx.x;
    if (e >= EE) return;
    int t = ei[EE + e];
    int s = ei[e];
    float f = g_d[e] * (1.0f / DELTA);
    int t0 = (int)(f + 0.5f);              // nearest table entry
    t0 = min(t0, NTAB - 1);
    int p = atomicAdd(&g_cnt[t], 1);
    g_perm[p] = (t0 << 14) | s;
}

__global__ void emb_kernel(const int* __restrict__ z, const float* __restrict__ emb) {
    int idx = blockIdx.x * blockDim.x + threadIdx.x;
    if (idx >= NN * HID) return;
    int n = idx >> 7, c = idx & 127;
    float v = emb[z[n] * HID + c];
    g_h[idx] = v;
    g_hb[idx] = __float2bfloat16(v);
}

// ---------------- weight preconversion: fp32 -> bf16 in fragment layout ----------------
// slot map: 0..11 Wl2[i](kh), 12..23 Wl[i](kh), 24..35 Wl1[i](kh),
//           36..37 Wo1(kh, NC=64), 38..43 Wf1[i](padded K), 44..55 Wf2[i](kh)
__global__ void convW_kernel(const float* __restrict__ Wl2, const float* __restrict__ Wl,
                             const float* __restrict__ Wl1, const float* __restrict__ Wo1,
                             const float* __restrict__ Wf1, const float* __restrict__ Wf2) {
    int slot = blockIdx.x;
    int tid = threadIdx.x;
    __nv_bfloat16* dst = g_Wc + (size_t)slot * SLOT_ELEMS;
    const float* src;
    int kh, NC = 128;
    bool padK = false;
    if (slot < 12)      { src = Wl2 + (size_t)(slot >> 1) * 16384; kh = slot & 1; }
    else if (slot < 24) { src = Wl  + (size_t)((slot - 12) >> 1) * 16384; kh = slot & 1; }
    else if (slot < 36) { src = Wl1 + (size_t)((slot - 24) >> 1) * 16384; kh = slot & 1; }
    else if (slot < 38) { src = Wo1; kh = slot - 36; NC = 64; }
    else if (slot < 44) { src = Wf1 + (size_t)(slot - 38) * NGAUSS * 128; kh = 0; padK = true; }
    else                { src = Wf2 + (size_t)((slot - 44) >> 1) * 16384; kh = slot & 1; }

    for (int flat = tid; flat < 128 * 64; flat += 256) {
        int n = flat >> 6, kp = flat & 63;
        int krow = kh * 64 + kp;
        float v = 0.0f;
        if (n < NC && !(padK && krow >= NGAUSS))
            v = src[(size_t)krow * NC + n];
        dst[n * 72 + kp] = __float2bfloat16(v);
    }
}

// ---------------- MMA helpers ----------------
#define MMA16816(d, a, b0, b1) \
    asm volatile("mma.sync.aligned.m16n8k16.row.col.f32.bf16.bf16.f32 " \
        "{%0,%1,%2,%3}, {%4,%5,%6,%7}, {%8,%9}, {%0,%1,%2,%3};" \
        : "+f"((d)[0]), "+f"((d)[1]), "+f"((d)[2]), "+f"((d)[3]) \
        : "r"((a)[0]), "r"((a)[1]), "r"((a)[2]), "r"((a)[3]), "r"(b0), "r"(b1))

// ---------------- preconverted-weight staging (pure copy, 9216 bf16 = 2304 uint2) ----------------
__device__ __forceinline__ void ldg_w(const __nv_bfloat16* __restrict__ src,
                                      uint2* wreg, int tid) {
    const uint2* s = (const uint2*)src;
#pragma unroll
    for (int i = 0; i < 9; i++) wreg[i] = s[tid + i * 256];
}
__device__ __forceinline__ void sts_w(const uint2* wreg, __nv_bfloat16* dst, int tid) {
    uint2* d = (uint2*)dst;
#pragma unroll
    for (int i = 0; i < 9; i++) d[tid + i * 256] = wreg[i];
}

template <int NT>
__device__ __forceinline__ void mma_half(
    const __nv_bfloat16* __restrict__ A, int lda, int kh,
    const __nv_bfloat16* W,
    int wm, int wn, int g, int tg, float acc[2][NT][4])
{
    const __nv_bfloat16* rp0 = A + (wm * 32 + g) * lda;
    const int colbase = wn * (NT * 8);
#pragma unroll
    for (int ks = 0; ks < 4; ks++) {
        int kc = kh * 64 + ks * 16 + tg * 2;
        uint32_t af[2][4];
#pragma unroll
        for (int mt = 0; mt < 2; mt++) {
            const __nv_bfloat16* rp = rp0 + mt * 16 * lda;
            af[mt][0] = *(const uint32_t*)(rp + kc);
            af[mt][1] = *(const uint32_t*)(rp + 8 * lda + kc);
            af[mt][2] = *(const uint32_t*)(rp + kc + 8);
            af[mt][3] = *(const uint32_t*)(rp + 8 * lda + kc + 8);
        }
        int c = ks * 16 + tg * 2;
#pragma unroll
        for (int nt = 0; nt < NT; nt++) {
            int n = colbase + nt * 8 + g;
            uint32_t b0 = *(const uint32_t*)(W + n * 72 + c);
            uint32_t b1 = *(const uint32_t*)(W + n * 72 + c + 8);
#pragma unroll
            for (int mt = 0; mt < 2; mt++) {
                MMA16816(acc[mt][nt], af[mt], b0, b1);
            }
        }
    }
}

// ---------------- filter-table builder: ea->GEMM->ssp->GEMM->cutoff ----------------
__global__ __launch_bounds__(256) void tableT_kernel(
    const float* __restrict__ bf1, const float* __restrict__ bf2)
{
    extern __shared__ __align__(16) char smem_raw[];
    __nv_bfloat16* sW0 = (__nv_bfloat16*)smem_raw;       // 9216
    __nv_bfloat16* sW1 = sW0 + SLOT_ELEMS;               // 9216
    __nv_bfloat16* sEa = sW1 + SLOT_ELEMS;               // 128*72
    __nv_bfloat16* sT  = sEa + 128 * 72;                 // 128*136

    const int tid = threadIdx.x;
    const int w = tid >> 5, lane = tid & 31;
    const int wm = w >> 1, wn = w & 1;
    const int g = lane >> 2, tg = lane & 3;
    const int inter = blockIdx.y;
    const int row0 = blockIdx.x * 128;

    const __nv_bfloat16* cWf1 = g_Wc + (size_t)(38 + inter) * SLOT_ELEMS;
    const __nv_bfloat16* cWf2 = g_Wc + (size_t)(44 + 2 * inter) * SLOT_ELEMS;
    const float* b1 = bf1 + (size_t)inter * HID;
    const float* b2 = bf2 + (size_t)inter * HID;

    // Gaussian rows (bf16, K padded to 64)
    for (int idx = tid; idx < 128 * 64; idx += 256) {
        int r = idx >> 6, k = idx & 63;
        float v = 0.0f;
        if (k < NGAUSS) {
            float u = (float)(row0 + r) * DELTA - (float)k * GSPACE;
            v = expf(GCOEFF * u * u);
        }
        sEa[r * 72 + k] = __float2bfloat16(v);
    }

    uint2 wreg[9];
    ldg_w(cWf1, wreg, tid);
    sts_w(wreg, sW0, tid);
    __syncthreads();

    // ---- GEMM1: H = ssp(ea @ Wf1 + bf1) -> sT ----
    {
        float acc1[2][8][4] = {};
        ldg_w(cWf2, wreg, tid);
        mma_half<8>(sEa, 72, 0, sW0, wm, wn, g, tg, acc1);
        sts_w(wreg, sW1, tid);
#pragma unroll
        for (int mt = 0; mt < 2; mt++) {
            int r0 = wm * 32 + mt * 16 + g;
            int r1 = r0 + 8;
#pragma unroll
            for (int nt = 0; nt < 8; nt++) {
                int cc = wn * 64 + nt * 8 + tg * 2;
                float2 bv = *(const float2*)(b1 + cc);
                float vx0 = sspf(acc1[mt][nt][0] + bv.x);
                float vy0 = sspf(acc1[mt][nt][1] + bv.y);
                float vx1 = sspf(acc1[mt][nt][2] + bv.x);
                float vy1 = sspf(acc1[mt][nt][3] + bv.y);
                *(__nv_bfloat162*)(sT + r0 * 136 + cc) = __floats2bfloat162_rn(vx0, vy0);
                *(__nv_bfloat162*)(sT + r1 * 136 + cc) = __floats2bfloat162_rn(vx1, vy1);
            }
        }
    }
    __syncthreads();

    // ---- GEMM2: T = (H @ Wf2 + bf2) * cutoff(row) -> g_Tb ----
    {
        float acc2[2][8][4] = {};
        ldg_w(cWf2 + SLOT_ELEMS, wreg, tid);
        mma_half<8>(sT, 136, 0, sW1, wm, wn, g, tg, acc2);
        sts_w(wreg, sW0, tid);
        __syncthreads();
        mma_half<8>(sT, 136, 1, sW0, wm, wn, g, tg, acc2);
        __nv_bfloat16* outB = g_Tb + (size_t)inter * NTAB * HID;
#pragma unroll
        for (int mt = 0; mt < 2; mt++) {
            int r0 = row0 + wm * 32 + mt * 16 + g;
            int r1 = r0 + 8;
            float s0 = 0.5f * (cosf((float)r0 * DELTA * PI_O10) + 1.0f);
            float s1 = 0.5f * (cosf((float)r1 * DELTA * PI_O10) + 1.0f);
#pragma unroll
            for (int nt = 0; nt < 8; nt++) {
                int cc = wn * 64 + nt * 8 + tg * 2;
                float2 bv = *(const float2*)(b2 + cc);
                float vx0 = (acc2[mt][nt][0] + bv.x) * s0;
                float vy0 = (acc2[mt][nt][1] + bv.y) * s0;
                float vx1 = (acc2[mt][nt][2] + bv.x) * s1;
                float vy1 = (acc2[mt][nt][3] + bv.y) * s1;
                *(__nv_bfloat162*)(outB + (size_t)r0 * 128 + cc) = __floats2bfloat162_rn(vx0, vy0);
                *(__nv_bfloat162*)(outB + (size_t)r1 * 128 + cc) = __floats2bfloat162_rn(vx1, vy1);
            }
        }
    }
}

// ---------------- standalone GEMM: x0 = hb @ Wl1[0] ----------------
__global__ __launch_bounds__(256) void gemm_x0(
    const __nv_bfloat16* __restrict__ A, __nv_bfloat16* __restrict__ outB)
{
    __shared__ __nv_bfloat16 sW[2 * SLOT_ELEMS];

    const int tid = threadIdx.x;
    const int w = tid >> 5, lane = tid & 31;
    const int wm = w >> 1, wn = w & 1;
    const int g = lane >> 2, tg = lane & 3;
    const int row0 = blockIdx.x * 128;

    const __nv_bfloat16* cW = g_Wc + (size_t)24 * SLOT_ELEMS;   // Wl1[0] kh0/kh1

    float acc[2][8][4] = {};
    const __nv_bfloat16* aBase = A + (size_t)row0 * 128;
    uint2 wreg[9];

    ldg_w(cW, wreg, tid);
    sts_w(wreg, sW, tid);
    __syncthreads();
    ldg_w(cW + SLOT_ELEMS, wreg, tid);
    mma_half<8>(aBase, 128, 0, sW, wm, wn, g, tg, acc);
    sts_w(wreg, sW + SLOT_ELEMS, tid);
    __syncthreads();
    mma_half<8>(aBase, 128, 1, sW + SLOT_ELEMS, wm, wn, g, tg, acc);

#pragma unroll
    for (int mt = 0; mt < 2; mt++) {
        int r0 = row0 + wm * 32 + mt * 16 + g;
        int r1 = r0 + 8;
#pragma unroll
        for (int nt = 0; nt < 8; nt++) {
            int cc = wn * 64 + nt * 8 + tg * 2;
            *(__nv_bfloat162*)(outB + (size_t)r0 * 128 + cc) =
                __floats2bfloat162_rn(acc[mt][nt][0], acc[mt][nt][1]);
            *(__nv_bfloat162*)(outB + (size_t)r1 * 128 + cc) =
                __floats2bfloat162_rn(acc[mt][nt][2], acc[mt][nt][3]);
        }
    }
}

// ---------------- fused interaction update: 3 chained GEMMs, copy-staged bf16 weights ----------------
template <bool LAST>
__global__ __launch_bounds__(256) void fused_update(
    const __nv_bfloat16* __restrict__ aggb,
    float* __restrict__ h,
    const __nv_bfloat16* __restrict__ cWl2, const float* __restrict__ bl2,
    const __nv_bfloat16* __restrict__ cWl,  const float* __restrict__ bl,
    const __nv_bfloat16* __restrict__ cW3,
    const float* __restrict__ bo1, const float* __restrict__ Wo2,
    __nv_bfloat16* __restrict__ xb)
{
    extern __shared__ __align__(16) char smem_raw[];
    __nv_bfloat16* sW0 = (__nv_bfloat16*)smem_raw;       // 9216
    __nv_bfloat16* sW1 = sW0 + SLOT_ELEMS;               // 9216
    __nv_bfloat16* sT  = sW1 + SLOT_ELEMS;               // 128*136
    __nv_bfloat16* sHn = sT + 128 * 136;                 // 128*136

    const int tid = threadIdx.x;
    const int w = tid >> 5, lane = tid & 31;
    const int wm = w >> 1, wn = w & 1;
    const int g = lane >> 2, tg = lane & 3;
    const int row0 = blockIdx.x * 128;

    uint2 wreg[9];
    const __nv_bfloat16* aggA = aggb + (size_t)row0 * 128;

    // preload (Wl2, kh0)
    ldg_w(cWl2, wreg, tid);
    sts_w(wreg, sW0, tid);
    __syncthreads();

    // ======== stage 1: t = ssp(aggb @ Wl2 + bl2) ========
    float acc1[2][8][4] = {};
    ldg_w(cWl2 + SLOT_ELEMS, wreg, tid);
    mma_half<8>(aggA, 128, 0, sW0, wm, wn, g, tg, acc1);
    sts_w(wreg, sW1, tid);
    __syncthreads();

    ldg_w(cWl, wreg, tid);
    mma_half<8>(aggA, 128, 1, sW1, wm, wn, g, tg, acc1);
    sts_w(wreg, sW0, tid);
    {
#pragma unroll
        for (int mt = 0; mt < 2; mt++) {
            int r0 = wm * 32 + mt * 16 + g;
            int r1 = r0 + 8;
#pragma unroll
            for (int nt = 0; nt < 8; nt++) {
                int cc = wn * 64 + nt * 8 + tg * 2;
                float2 bv = *(const float2*)(bl2 + cc);
                float vx0 = sspf(acc1[mt][nt][0] + bv.x);
                float vy0 = sspf(acc1[mt][nt][1] + bv.y);
                float vx1 = sspf(acc1[mt][nt][2] + bv.x);
                float vy1 = sspf(acc1[mt][nt][3] + bv.y);
                *(__nv_bfloat162*)(sT + r0 * 136 + cc) = __floats2bfloat162_rn(vx0, vy0);
                *(__nv_bfloat162*)(sT + r1 * 136 + cc) = __floats2bfloat162_rn(vx1, vy1);
            }
        }
    }
    __syncthreads();

    // ======== stage 2: hn = t @ Wl + bl + h ========
    float acc2[2][8][4] = {};
    ldg_w(cWl + SLOT_ELEMS, wreg, tid);
    mma_half<8>(sT, 136, 0, sW0, wm, wn, g, tg, acc2);
    sts_w(wreg, sW1, tid);
    __syncthreads();

    ldg_w(cW3, wreg, tid);
    mma_half<8>(sT, 136, 1, sW1, wm, wn, g, tg, acc2);
    sts_w(wreg, sW0, tid);
    {
#pragma unroll
        for (int mt = 0; mt < 2; mt++) {
            int r0 = wm * 32 + mt * 16 + g;
            int r1 = r0 + 8;
            float* h0p = h + (size_t)(row0 + r0) * 128;
            float* h1p = h + (size_t)(row0 + r1) * 128;
#pragma unroll
            for (int nt = 0; nt < 8; nt++) {
                int cc = wn * 64 + nt * 8 + tg * 2;
                float2 bv = *(const float2*)(bl + cc);
                float2 e0 = *(const float2*)(h0p + cc);
                float2 e1 = *(const float2*)(h1p + cc);
                float vx0 = acc2[mt][nt][0] + bv.x + e0.x;
                float vy0 = acc2[mt][nt][1] + bv.y + e0.y;
                float vx1 = acc2[mt][nt][2] + bv.x + e1.x;
                float vy1 = acc2[mt][nt][3] + bv.y + e1.y;
                *(float2*)(h0p + cc) = make_float2(vx0, vy0);
                *(float2*)(h1p + cc) = make_float2(vx1, vy1);
                *(__nv_bfloat162*)(sHn + r0 * 136 + cc) = __floats2bfloat162_rn(vx0, vy0);
                *(__nv_bfloat162*)(sHn + r1 * 136 + cc) = __floats2bfloat162_rn(vx1, vy1);
            }
        }
    }
    __syncthreads();

    // ======== stage 3: next x or readout ========
    if (!LAST) {
        float acc3[2][8][4] = {};
        ldg_w(cW3 + SLOT_ELEMS, wreg, tid);
        mma_half<8>(sHn, 136, 0, sW0, wm, wn, g, tg, acc3);
        sts_w(wreg, sW1, tid);
        __syncthreads();
        mma_half<8>(sHn, 136, 1, sW1, wm, wn, g, tg, acc3);
#pragma unroll
        for (int mt = 0; mt < 2; mt++) {
            int r0 = row0 + wm * 32 + mt * 16 + g;
            int r1 = r0 + 8;
#pragma unroll
            for (int nt = 0; nt < 8; nt++) {
                int cc = wn * 64 + nt * 8 + tg * 2;
                *(__nv_bfloat162*)(xb + (size_t)r0 * 128 + cc) =
                    __floats2bfloat162_rn(acc3[mt][nt][0], acc3[mt][nt][1]);
                *(__nv_bfloat162*)(xb + (size_t)r1 * 128 + cc) =
                    __floats2bfloat162_rn(acc3[mt][nt][2], acc3[mt][nt][3]);
            }
        }
    } else {
        float acc3[2][4][4] = {};
        ldg_w(cW3 + SLOT_ELEMS, wreg, tid);
        mma_half<4>(sHn, 136, 0, sW0, wm, wn, g, tg, acc3);
        sts_w(wreg, sW1, tid);
        __syncthreads();
        mma_half<4>(sHn, 136, 1, sW1, wm, wn, g, tg, acc3);
        float v = 0.0f;
#pragma unroll
        for (int mt = 0; mt < 2; mt++) {
#pragma unroll
            for (int nt = 0; nt < 4; nt++) {
                int cc = wn * 32 + nt * 8 + tg * 2;
                float2 bo = *(const float2*)(bo1 + cc);
                float2 w2 = *(const float2*)(Wo2 + cc);
                v += sspf(acc3[mt][nt][0] + bo.x) * w2.x + sspf(acc3[mt][nt][1] + bo.y) * w2.y;
                v += sspf(acc3[mt][nt][2] + bo.x) * w2.x + sspf(acc3[mt][nt][3] + bo.y) * w2.y;
            }
        }
#pragma unroll
        for (int off = 16; off > 0; off >>= 1)
            v += __shfl_xor_sync(0xFFFFFFFFu, v, off);
        if (lane == 0) atomicAdd(&g_sum, v);
    }
}

// ---------------- edge aggregation (dst-sorted, warp/node, nearest table) ----------------
__device__ __forceinline__ void edge_acc(const __nv_bfloat16* xb, const __nv_bfloat16* Tb,
                                         int pk, int lane, float4& acc) {
    int s = pk & 16383;
    int t0 = pk >> 14;
    uint2 xv = ((const uint2*)(xb + (size_t)s * 128))[lane];
    uint2 tv = ((const uint2*)(Tb + (size_t)t0 * 128))[lane];
    float2 x0 = __bfloat1622float2(*(__nv_bfloat162*)&xv.x);
    float2 x1 = __bfloat1622float2(*(__nv_bfloat162*)&xv.y);
    float2 f0 = __bfloat1622float2(*(__nv_bfloat162*)&tv.x);
    float2 f1 = __bfloat1622float2(*(__nv_bfloat162*)&tv.y);
    acc.x += x0.x * f0.x;
    acc.y += x0.y * f0.y;
    acc.z += x1.x * f1.x;
    acc.w += x1.y * f1.y;
}

__global__ void agg_kernel(const __nv_bfloat16* __restrict__ xb,
                           const __nv_bfloat16* __restrict__ Tb) {
    int warp = (blockIdx.x * blockDim.x + threadIdx.x) >> 5;
    int lane = threadIdx.x & 31;
    if (warp >= NN) return;
    int b = g_start[warp];
    int e = b + g_len[warp];
    float4 acc = make_float4(0.f, 0.f, 0.f, 0.f);
    int j = b;
    for (; j + 4 <= e; j += 4) {
        int pk0 = g_perm[j],     pk1 = g_perm[j + 1];
        int pk2 = g_perm[j + 2], pk3 = g_perm[j + 3];
        edge_acc(xb, Tb, pk0, lane, acc);
        edge_acc(xb, Tb, pk1, lane, acc);
        edge_acc(xb, Tb, pk2, lane, acc);
        edge_acc(xb, Tb, pk3, lane, acc);
    }
    for (; j < e; j++) edge_acc(xb, Tb, g_perm[j], lane, acc);
    __nv_bfloat162 o0 = __floats2bfloat162_rn(acc.x, acc.y);
    __nv_bfloat162 o1 = __floats2bfloat162_rn(acc.z, acc.w);
    uint2 ov;
    ov.x = *(uint32_t*)&o0;
    ov.y = *(uint32_t*)&o1;
    ((uint2*)(g_aggb + (size_t)warp * 128))[lane] = ov;
}

__global__ void final_kernel(float* __restrict__ out, const float* __restrict__ bo2) {
    float v = g_sum + (float)NN * bo2[0];
    out[0] = fmaxf(v, 0.0f);
}

// ---------------- launch ----------------
extern "C" void kernel_launch(void* const* d_in, const int* in_sizes, int n_in,
                              void* d_out, int out_size) {
    const int*   z    = (const int*)d_in[0];
    const float* pos  = (const float*)d_in[1];
    const int*   ei   = (const int*)d_in[2];
    const float* emb  = (const float*)d_in[3];
    const float* Wf1  = (const float*)d_in[4];
    const float* bf1  = (const float*)d_in[5];
    const float* Wf2  = (const float*)d_in[6];
    const float* bf2  = (const float*)d_in[7];
    const float* Wl1  = (const float*)d_in[8];
    const float* Wl2  = (const float*)d_in[9];
    const float* bl2  = (const float*)d_in[10];
    const float* Wl   = (const float*)d_in[11];
    const float* bl   = (const float*)d_in[12];
    const float* Wo1  = (const float*)d_in[13];
    const float* bo1  = (const float*)d_in[14];
    const float* Wo2  = (const float*)d_in[15];
    const float* bo2  = (const float*)d_in[16];
    float* out = (float*)d_out;

    float *p_h;
    __nv_bfloat16 *p_hb, *p_xb, *p_aggb, *p_Tb, *p_Wc;
    cudaGetSymbolAddress((void**)&p_h,    g_h);
    cudaGetSymbolAddress((void**)&p_hb,   g_hb);
    cudaGetSymbolAddress((void**)&p_xb,   g_xb);
    cudaGetSymbolAddress((void**)&p_aggb, g_aggb);
    cudaGetSymbolAddress((void**)&p_Tb,   g_Tb);
    cudaGetSymbolAddress((void**)&p_Wc,   g_Wc);

    const int FUSED_SMEM = (2 * SLOT_ELEMS + 2 * 128 * 136) * (int)sizeof(__nv_bfloat16);
    const int TABLE_SMEM = (2 * SLOT_ELEMS + 128 * 72 + 128 * 136) * (int)sizeof(__nv_bfloat16);
    cudaFuncSetAttribute(fused_update<false>, cudaFuncAttributeMaxDynamicSharedMemorySize, FUSED_SMEM);
    cudaFuncSetAttribute(fused_update<true>,  cudaFuncAttributeMaxDynamicSharedMemorySize, FUSED_SMEM);
    cudaFuncSetAttribute(tableT_kernel, cudaFuncAttributeMaxDynamicSharedMemorySize, TABLE_SMEM);

    // --- weight preconversion (independent; head of graph) ---
    convW_kernel<<<NSLOT, 256>>>(Wl2, Wl, Wl1, Wo1, Wf1, Wf2);

    // --- edge prep + dst sort ---
    zero_kernel<<<NN / 256, 256>>>();
    prep_kernel<<<EE / 256, 256>>>(pos, ei);
    scan_kernel<<<NN / 256, 256>>>();
    scatter_kernel<<<EE / 256, 256>>>(ei);
    emb_kernel<<<NN * HID / 256, 256>>>(z, emb);

    // --- filter tables, all-MMA (batched over 6 interactions) ---
    tableT_kernel<<<dim3(NTAB / 128, NINTER), 256, TABLE_SMEM>>>(bf1, bf2);

    // --- first x = h @ Wl1[0] ---
    gemm_x0<<<NN / 128, 256>>>(p_hb, p_xb);

    // --- interaction blocks: agg + fused pipelined update ---
    for (int i = 0; i < NINTER; i++) {
        agg_kernel<<<NN / 8, 256>>>(p_xb, p_Tb + (size_t)i * NTAB * HID);
        const __nv_bfloat16* cWl2 = p_Wc + (size_t)(2 * i) * SLOT_ELEMS;
        const __nv_bfloat16* cWl  = p_Wc + (size_t)(12 + 2 * i) * SLOT_ELEMS;
        if (i < NINTER - 1) {
            const __nv_bfloat16* cW3 = p_Wc + (size_t)(24 + 2 * (i + 1)) * SLOT_ELEMS;
            fused_update<false><<<NN / 128, 256, FUSED_SMEM>>>(
                p_aggb, p_h,
                cWl2, bl2 + (size_t)i * HID,
                cWl,  bl  + (size_t)i * HID,
                cW3, nullptr, nullptr, p_xb);
        } else {
            const __nv_bfloat16* cW3 = p_Wc + (size_t)36 * SLOT_ELEMS;
            fused_update<true><<<NN / 128, 256, FUSED_SMEM>>>(
                p_aggb, p_h,
                cWl2, bl2 + (size_t)i * HID,
                cWl,  bl  + (size_t)i * HID,
                cW3, bo1, Wo2, nullptr);
        }
    }

    final_kernel<<<1, 1>>>(out, bo2);
}